// round 8
// baseline (speedup 1.0000x reference)
#include <cuda_runtime.h>
#include <cuda_bf16.h>

#define B_   4
#define S_   2048
#define D_   1024
#define M_   (B_ * S_)          // 8192
#define NCH  16
#define CH   (S_ / NCH)         // 128
#define SC   1024.0f            // lo-part scale (2^10)
#define ISC  (1.0f / 1024.0f)

// ---------------- scratch ----------------------------------------------------
// hi operands: bf16 K-major. cross operands: packed fp8 pairs, one u16 per orig-k
//   A-side u16: byte0 = e4m3(hi), byte1 = e4m3(lo*SC)
//   B-side u16: byte0 = e4m3(lo*SC), byte1 = e4m3(hi)
__device__ __align__(256) __nv_bfloat16  g_qh  [(size_t)M_ * D_];
__device__ __align__(256) unsigned short g_qx  [(size_t)M_ * D_];
__device__ __align__(256) __nv_bfloat16  g_avgh[(size_t)M_ * D_];
__device__ __align__(256) unsigned short g_avgx[(size_t)M_ * D_];
__device__ __align__(256) __nv_bfloat16  g_hh  [(size_t)M_ * D_];
__device__ __align__(256) unsigned short g_hx  [(size_t)M_ * D_];
__device__ __align__(256) __nv_bfloat16  g_fh  [(size_t)M_ * D_];
__device__ __align__(256) unsigned short g_fx  [(size_t)M_ * D_];
__device__ __align__(256) __nv_bfloat16  g_W1h [(size_t)D_ * D_];
__device__ __align__(256) unsigned short g_W1x [(size_t)D_ * D_];
__device__ __align__(256) __nv_bfloat16  g_W2h [(size_t)D_ * D_];
__device__ __align__(256) unsigned short g_W2x [(size_t)D_ * D_];
__device__ __align__(256) __nv_bfloat16  g_Wgh [(size_t)2 * D_ * 2 * D_];
__device__ __align__(256) unsigned short g_Wgx [(size_t)2 * D_ * 2 * D_];
__device__ __align__(256) float g_ffn [(size_t)M_ * D_];
__device__ float g_part[B_ * NCH * D_];

// ---------------- helpers ----------------------------------------------------
__device__ __forceinline__ unsigned smem_u32(const void* p) {
    unsigned r;
    asm("{ .reg .u64 t; cvta.to.shared.u64 t, %1; cvt.u32.u64 %0, t; }" : "=r"(r) : "l"(p));
    return r;
}
// pack two floats to e4m3x2: upper byte = e4m3(a), lower byte = e4m3(b)
__device__ __forceinline__ unsigned short pk_e4m3(float a, float b) {
    unsigned short r;
    asm("cvt.rn.satfinite.e4m3x2.f32 %0, %1, %2;" : "=h"(r) : "f"(a), "f"(b));
    return r;
}
// split x into bf16 hi + float residual
__device__ __forceinline__ void split2(float x, __nv_bfloat16& hb, float& lo) {
    hb = __float2bfloat16_rn(x);
    lo = x - __bfloat162float(hb);
}
__device__ __forceinline__ unsigned short a_pack(float x) {   // A-side cross u16
    __nv_bfloat16 hb; float lo; split2(x, hb, lo);
    return pk_e4m3(lo * SC, __bfloat162float(hb));
}
__device__ __forceinline__ unsigned short b_pack(float x) {   // B-side cross u16
    __nv_bfloat16 hb; float lo; split2(x, hb, lo);
    return pk_e4m3(__bfloat162float(hb), lo * SC);
}
__device__ __forceinline__ void ldsm4(unsigned& r0, unsigned& r1, unsigned& r2, unsigned& r3,
                                      unsigned addr) {
    asm volatile("ldmatrix.sync.aligned.m8n8.x4.shared.b16 {%0,%1,%2,%3}, [%4];"
                 : "=r"(r0), "=r"(r1), "=r"(r2), "=r"(r3) : "r"(addr));
}
__device__ __forceinline__ void mma_bf16(float* c, unsigned a0, unsigned a1, unsigned a2,
                                         unsigned a3, unsigned b0, unsigned b1) {
    asm volatile(
        "mma.sync.aligned.m16n8k16.row.col.f32.bf16.bf16.f32 "
        "{%0,%1,%2,%3}, {%4,%5,%6,%7}, {%8,%9}, {%0,%1,%2,%3};"
        : "+f"(c[0]), "+f"(c[1]), "+f"(c[2]), "+f"(c[3])
        : "r"(a0), "r"(a1), "r"(a2), "r"(a3), "r"(b0), "r"(b1));
}
__device__ __forceinline__ void mma_fp8(float* c, unsigned a0, unsigned a1, unsigned a2,
                                        unsigned a3, unsigned b0, unsigned b1) {
    asm volatile(
        "mma.sync.aligned.m16n8k32.row.col.f32.e4m3.e4m3.f32 "
        "{%0,%1,%2,%3}, {%4,%5,%6,%7}, {%8,%9}, {%0,%1,%2,%3};"
        : "+f"(c[0]), "+f"(c[1]), "+f"(c[2]), "+f"(c[3])
        : "r"(a0), "r"(a1), "r"(a2), "r"(a3), "r"(b0), "r"(b1));
}

// ---------------- scan: causal cumulative mean -------------------------------
__global__ void k_partial_sums(const float* __restrict__ iV) {
    int b = blockIdx.x, ch = blockIdx.y, d = threadIdx.x;
    const float* p = iV + ((size_t)b * S_ + (size_t)ch * CH) * D_ + d;
    float s = 0.f;
#pragma unroll 8
    for (int t = 0; t < CH; t++) s += p[(size_t)t * D_];
    g_part[(b * NCH + ch) * D_ + d] = s;
}

__global__ void k_exclusive_prefix() {
    int b = blockIdx.x, d = threadIdx.x;
    float run = 0.f;
#pragma unroll
    for (int ch = 0; ch < NCH; ch++) {
        int idx = (b * NCH + ch) * D_ + d;
        float v = g_part[idx];
        g_part[idx] = run;
        run += v;
    }
}

__global__ void k_cumavg(const float* __restrict__ iV) {
    int b = blockIdx.x, ch = blockIdx.y, d = threadIdx.x;
    float run = g_part[(b * NCH + ch) * D_ + d];
    const float* p = iV + ((size_t)b * S_ + (size_t)ch * CH) * D_ + d;
    size_t mrow = (size_t)b * S_ + (size_t)ch * CH;
#pragma unroll 4
    for (int t = 0; t < CH; t++) {
        run += p[(size_t)t * D_];
        int s = ch * CH + t;
        float x = run * (1.0f / (float)(s + 1));
        __nv_bfloat16 hb; float lo; split2(x, hb, lo);
        size_t idx = (mrow + t) * D_ + d;
        g_avgh[idx] = hb;
        g_avgx[idx] = pk_e4m3(lo * SC, __bfloat162float(hb));
    }
}

// ---------------- conversions ------------------------------------------------
// iQ fp32 -> (g_qh bf16, g_qx fp8-pair), 32 elements per thread
__global__ __launch_bounds__(256) void k_convert_iQ(const float* __restrict__ iQ) {
    size_t t = (size_t)blockIdx.x * blockDim.x + threadIdx.x;   // M_*D_/32 threads
    size_t m  = t / (D_ / 32);
    int    dq = (int)(t % (D_ / 32)) * 32;
    const float4* src = (const float4*)(iQ + m * D_ + dq);
    unsigned hw[16], xw[16];
#pragma unroll
    for (int i = 0; i < 8; i++) {
        float4 x = src[i];
        unsigned short h0 = __bfloat16_as_ushort(__float2bfloat16_rn(x.x));
        unsigned short h1 = __bfloat16_as_ushort(__float2bfloat16_rn(x.y));
        unsigned short h2 = __bfloat16_as_ushort(__float2bfloat16_rn(x.z));
        unsigned short h3 = __bfloat16_as_ushort(__float2bfloat16_rn(x.w));
        hw[2 * i]     = (unsigned)h0 | ((unsigned)h1 << 16);
        hw[2 * i + 1] = (unsigned)h2 | ((unsigned)h3 << 16);
        xw[2 * i]     = (unsigned)a_pack(x.x) | ((unsigned)a_pack(x.y) << 16);
        xw[2 * i + 1] = (unsigned)a_pack(x.z) | ((unsigned)a_pack(x.w) << 16);
    }
    uint4* dh = (uint4*)(g_qh + m * D_ + dq);
    uint4* dx = (uint4*)(g_qx + m * D_ + dq);
#pragma unroll
    for (int i = 0; i < 4; i++) {
        dh[i] = make_uint4(hw[4 * i], hw[4 * i + 1], hw[4 * i + 2], hw[4 * i + 3]);
        dx[i] = make_uint4(xw[4 * i], xw[4 * i + 1], xw[4 * i + 2], xw[4 * i + 3]);
    }
}

// W [K,N] fp32 -> (Wh bf16 [N,K], Wx fp8-pair [N,K]) via smem transpose
__global__ __launch_bounds__(256) void k_convert_W(const float* __restrict__ W,
                                                   __nv_bfloat16* __restrict__ Wh,
                                                   unsigned short* __restrict__ Wx,
                                                   int K, int N) {
    __shared__ float t[64][65];
    const int tid = threadIdx.x;
    const int n0 = blockIdx.x * 64, k0 = blockIdx.y * 64;
    {
        const int r = tid >> 4;
        const int c4 = tid & 15;
#pragma unroll
        for (int i = 0; i < 4; i++) {
            int k = r + 16 * i;
            float4 v = *(const float4*)(W + (size_t)(k0 + k) * N + n0 + 4 * c4);
            t[k][4 * c4 + 0] = v.x;
            t[k][4 * c4 + 1] = v.y;
            t[k][4 * c4 + 2] = v.z;
            t[k][4 * c4 + 3] = v.w;
        }
    }
    __syncthreads();
    const int n = tid >> 2;
    const int kq = tid & 3;
    unsigned hw[8], xw[8];
#pragma unroll
    for (int j = 0; j < 8; j++) {
        float x0 = t[16 * kq + 2 * j][n];
        float x1 = t[16 * kq + 2 * j + 1][n];
        unsigned short h0 = __bfloat16_as_ushort(__float2bfloat16_rn(x0));
        unsigned short h1 = __bfloat16_as_ushort(__float2bfloat16_rn(x1));
        hw[j] = (unsigned)h0 | ((unsigned)h1 << 16);
        xw[j] = (unsigned)b_pack(x0) | ((unsigned)b_pack(x1) << 16);
    }
    uint4* dh = (uint4*)(Wh + (size_t)(n0 + n) * K + k0 + 16 * kq);
    uint4* dx = (uint4*)(Wx + (size_t)(n0 + n) * K + k0 + 16 * kq);
#pragma unroll
    for (int i = 0; i < 2; i++) {
        dh[i] = make_uint4(hw[4 * i], hw[4 * i + 1], hw[4 * i + 2], hw[4 * i + 3]);
        dx[i] = make_uint4(xw[4 * i], xw[4 * i + 1], xw[4 * i + 2], xw[4 * i + 3]);
    }
}

// ---------------- dual-precision GEMM (128x128 tile, 256 threads) -------------
// acc = Ah@Bh (bf16 k16)  +  ISC * Ax@Bx (fp8 k32, interleaved cross terms)
// SEL 0: avg @ W1 -> relu+b1 -> (g_hh, g_hx)
// SEL 1: h   @ W2 -> +b2    -> g_ffn fp32 + (g_fh, g_fx)
// SEL 2: concat(q, ffn) @ Wg (paired cols) -> sigmoid -> smem exchange ->
//        out = igate*iQ + fgate*ffn
#define BKO 64                               // orig-k per block (128 B rows)
#define STAGES 3
#define T_BYTES (128 * 128)                  // 16 KB per operand tile
#define STG_BYTES (4 * T_BYTES)              // Ah, Ax, Bh, Bx = 64 KB
#define SMEM_DYN (STAGES * STG_BYTES)        // 192 KB

template <int SEL>
__global__ __launch_bounds__(256, 1)
void k_gemm_mma(const __nv_bfloat16* __restrict__ Ah0,
                const unsigned short* __restrict__ Ax0,
                const __nv_bfloat16* __restrict__ Ah1,
                const unsigned short* __restrict__ Ax1,
                const __nv_bfloat16* __restrict__ Wh,
                const unsigned short* __restrict__ Wx,
                const float* __restrict__ bias,
                int K,                        // orig K (B row length)
                const float* __restrict__ iQf,
                float* __restrict__ out)
{
    extern __shared__ __align__(1024) char dsmem[];
    const unsigned sbase = smem_u32(dsmem);

    const int tid = threadIdx.x;
    const int warp = tid >> 5, lid = tid & 31;
    const int wm = warp >> 2;            // 0..1 -> 64 rows
    const int wn = warp & 3;             // 0..3 -> 32 cols
    const int m0 = blockIdx.y * 128;
    const int n0 = blockIdx.x * 128;     // SEL0/1
    const int cg0 = blockIdx.x * 64;     // SEL2 gate col-pair base
    const int NB = K / BKO;

    const int lrow = tid >> 1;           // 0..127
    const int lcb  = (tid & 1) * 4;      // chunk base
    const int lswz = lrow & 7;

    float accH[4][4][4], accX[4][4][4];
#pragma unroll
    for (int i = 0; i < 4; i++)
#pragma unroll
        for (int j = 0; j < 4; j++)
#pragma unroll
            for (int k = 0; k < 4; k++) { accH[i][j][k] = 0.f; accX[i][j][k] = 0.f; }

    auto load_blk = [&](int kb, int stage) {
        unsigned s0 = sbase + stage * STG_BYTES;
        const __nv_bfloat16* Ah; const unsigned short* Ax;
        int kc = kb;
        if (SEL == 2 && kb >= 16) { Ah = Ah1; Ax = Ax1; kc = kb - 16; }
        else                      { Ah = Ah0; Ax = Ax0; }
        unsigned long long agh = (unsigned long long)(Ah + (size_t)(m0 + lrow) * D_ + kc * BKO);
        unsigned long long agx = (unsigned long long)(Ax + (size_t)(m0 + lrow) * D_ + kc * BKO);
        int gn;
        if (SEL == 2) gn = (lrow < 64) ? (cg0 + lrow) : (1024 + cg0 + lrow - 64);
        else          gn = n0 + lrow;
        unsigned long long bgh = (unsigned long long)(Wh + (size_t)gn * K + kb * BKO);
        unsigned long long bgx = (unsigned long long)(Wx + (size_t)gn * K + kb * BKO);
        unsigned dAh = s0 + lrow * 128;
        unsigned dAx = dAh + T_BYTES;
        unsigned dBh = dAx + T_BYTES;
        unsigned dBx = dBh + T_BYTES;
#pragma unroll
        for (int i = 0; i < 4; i++) {
            int c = lcb + i;
            unsigned off = (unsigned)((c ^ lswz) << 4);
            asm volatile("cp.async.cg.shared.global [%0], [%1], 16;"
                         :: "r"(dAh + off), "l"(agh + c * 16) : "memory");
            asm volatile("cp.async.cg.shared.global [%0], [%1], 16;"
                         :: "r"(dAx + off), "l"(agx + c * 16) : "memory");
            asm volatile("cp.async.cg.shared.global [%0], [%1], 16;"
                         :: "r"(dBh + off), "l"(bgh + c * 16) : "memory");
            asm volatile("cp.async.cg.shared.global [%0], [%1], 16;"
                         :: "r"(dBx + off), "l"(bgx + c * 16) : "memory");
        }
        asm volatile("cp.async.commit_group;" ::: "memory");
    };

    // ---- fragment addressing ----
    int arow[4], brow[2];
#pragma unroll
    for (int mt = 0; mt < 4; mt++)
        arow[mt] = wm * 64 + mt * 16 + (lid & 7) + ((lid >> 3) & 1) * 8;
    const int ahi = lid >> 4;
#pragma unroll
    for (int p = 0; p < 2; p++)
        brow[p] = wn * 32 + p * 16 + (lid & 7) + (lid >> 4) * 8;
    const int bhi = (lid >> 3) & 1;

    // ---- prologue ----
#pragma unroll
    for (int s = 0; s < STAGES - 1; s++) load_blk(s, s);

    for (int kb = 0; kb < NB; kb++) {
        asm volatile("cp.async.wait_group %0;" :: "n"(STAGES - 2) : "memory");
        __syncthreads();
        if (kb + STAGES - 1 < NB) load_blk(kb + STAGES - 1, (kb + STAGES - 1) % STAGES);

        unsigned s0 = sbase + (kb % STAGES) * STG_BYTES;
        unsigned sAh = s0, sAx = s0 + T_BYTES, sBh = s0 + 2 * T_BYTES, sBx = s0 + 3 * T_BYTES;

        // hi terms: bf16 k16, 4 steps
#pragma unroll
        for (int ks = 0; ks < 4; ks++) {
            unsigned a[4][4], b[2][4];
#pragma unroll
            for (int mt = 0; mt < 4; mt++)
                ldsm4(a[mt][0], a[mt][1], a[mt][2], a[mt][3],
                      sAh + arow[mt] * 128 + (unsigned)(((2 * ks + ahi) ^ (arow[mt] & 7)) << 4));
#pragma unroll
            for (int p = 0; p < 2; p++)
                ldsm4(b[p][0], b[p][1], b[p][2], b[p][3],
                      sBh + brow[p] * 128 + (unsigned)(((2 * ks + bhi) ^ (brow[p] & 7)) << 4));
#pragma unroll
            for (int mt = 0; mt < 4; mt++)
#pragma unroll
                for (int nt = 0; nt < 4; nt++)
                    mma_bf16(accH[mt][nt], a[mt][0], a[mt][1], a[mt][2], a[mt][3],
                             b[nt >> 1][(nt & 1) * 2], b[nt >> 1][(nt & 1) * 2 + 1]);
        }
        // cross terms: fp8 k32, 4 steps (byte-identical fragment addressing)
#pragma unroll
        for (int ks = 0; ks < 4; ks++) {
            unsigned a[4][4], b[2][4];
#pragma unroll
            for (int mt = 0; mt < 4; mt++)
                ldsm4(a[mt][0], a[mt][1], a[mt][2], a[mt][3],
                      sAx + arow[mt] * 128 + (unsigned)(((2 * ks + ahi) ^ (arow[mt] & 7)) << 4));
#pragma unroll
            for (int p = 0; p < 2; p++)
                ldsm4(b[p][0], b[p][1], b[p][2], b[p][3],
                      sBx + brow[p] * 128 + (unsigned)(((2 * ks + bhi) ^ (brow[p] & 7)) << 4));
#pragma unroll
            for (int mt = 0; mt < 4; mt++)
#pragma unroll
                for (int nt = 0; nt < 4; nt++)
                    mma_fp8(accX[mt][nt], a[mt][0], a[mt][1], a[mt][2], a[mt][3],
                            b[nt >> 1][(nt & 1) * 2], b[nt >> 1][(nt & 1) * 2 + 1]);
        }
    }

    // ---- epilogue ----
    const int gid = lid >> 2, tig = lid & 3;

    if (SEL == 2) {
        __syncthreads();
        float* gsm = (float*)dsmem;        // [128][132]
#pragma unroll
        for (int mt = 0; mt < 4; mt++) {
#pragma unroll
            for (int r2 = 0; r2 < 2; r2++) {
                const int ml = wm * 64 + mt * 16 + gid + r2 * 8;
#pragma unroll
                for (int nt = 0; nt < 4; nt++) {
                    const int nl = wn * 32 + nt * 8 + 2 * tig;
                    const int gcol = (nl < 64) ? (cg0 + nl) : (1024 + cg0 + nl - 64);
                    float2 bb = *(const float2*)(bias + gcol);
                    float v0 = accH[mt][nt][r2 * 2 + 0] + ISC * accX[mt][nt][r2 * 2 + 0] + bb.x;
                    float v1 = accH[mt][nt][r2 * 2 + 1] + ISC * accX[mt][nt][r2 * 2 + 1] + bb.y;
                    v0 = 1.0f / (1.0f + __expf(-v0));
                    v1 = 1.0f / (1.0f + __expf(-v1));
                    gsm[ml * 132 + nl]     = v0;
                    gsm[ml * 132 + nl + 1] = v1;
                }
            }
        }
        __syncthreads();
        const int c4 = tid & 15;            // 16 float4 col groups -> 64 cols
        const int r0 = tid >> 4;            // 0..15
#pragma unroll
        for (int i = 0; i < 8; i++) {
            const int r = r0 + 16 * i;
            const int col = 4 * c4;
            const size_t gidx = (size_t)(m0 + r) * D_ + cg0 + col;
            float4 q = *(const float4*)(iQf + gidx);
            float4 f = *(const float4*)(g_ffn + gidx);
            float4 gi = *(const float4*)&gsm[r * 132 + col];
            float4 gf = *(const float4*)&gsm[r * 132 + 64 + col];
            float4 o;
            o.x = gi.x * q.x + gf.x * f.x;
            o.y = gi.y * q.y + gf.y * f.y;
            o.z = gi.z * q.z + gf.z * f.z;
            o.w = gi.w * q.w + gf.w * f.w;
            *(float4*)(out + gidx) = o;
        }
        return;
    }

#pragma unroll
    for (int mt = 0; mt < 4; mt++) {
#pragma unroll
        for (int r2 = 0; r2 < 2; r2++) {
            const int m = m0 + wm * 64 + mt * 16 + gid + r2 * 8;
#pragma unroll
            for (int nt = 0; nt < 4; nt++) {
                const int n = n0 + wn * 32 + nt * 8 + 2 * tig;
                float2 bb = *(const float2*)(bias + n);
                float v0 = accH[mt][nt][r2 * 2 + 0] + ISC * accX[mt][nt][r2 * 2 + 0] + bb.x;
                float v1 = accH[mt][nt][r2 * 2 + 1] + ISC * accX[mt][nt][r2 * 2 + 1] + bb.y;
                if (SEL == 0) { v0 = fmaxf(v0, 0.f); v1 = fmaxf(v1, 0.f); }
                else          *(float2*)(g_ffn + (size_t)m * D_ + n) = make_float2(v0, v1);
                unsigned short h0 = __bfloat16_as_ushort(__float2bfloat16_rn(v0));
                unsigned short h1 = __bfloat16_as_ushort(__float2bfloat16_rn(v1));
                unsigned hw = (unsigned)h0 | ((unsigned)h1 << 16);
                unsigned xw = (unsigned)a_pack(v0) | ((unsigned)a_pack(v1) << 16);
                if (SEL == 0) {
                    *(unsigned*)(g_hh + (size_t)m * D_ + n) = hw;
                    *(unsigned*)(g_hx + (size_t)m * D_ + n) = xw;
                } else {
                    *(unsigned*)(g_fh + (size_t)m * D_ + n) = hw;
                    *(unsigned*)(g_fx + (size_t)m * D_ + n) = xw;
                }
            }
        }
    }
}

// ---------------- launch ------------------------------------------------------
extern "C" void kernel_launch(void* const* d_in, const int* in_sizes, int n_in,
                              void* d_out, int out_size) {
    const float* iQ = (const float*)d_in[0];
    const float* iV = (const float*)d_in[1];
    const float* W1 = (const float*)d_in[2];
    const float* b1 = (const float*)d_in[3];
    const float* W2 = (const float*)d_in[4];
    const float* b2 = (const float*)d_in[5];
    const float* Wg = (const float*)d_in[6];
    const float* bg = (const float*)d_in[7];
    float* out = (float*)d_out;

    cudaFuncSetAttribute(k_gemm_mma<0>, cudaFuncAttributeMaxDynamicSharedMemorySize, SMEM_DYN);
    cudaFuncSetAttribute(k_gemm_mma<1>, cudaFuncAttributeMaxDynamicSharedMemorySize, SMEM_DYN);
    cudaFuncSetAttribute(k_gemm_mma<2>, cudaFuncAttributeMaxDynamicSharedMemorySize, SMEM_DYN);

    __nv_bfloat16 *w1h, *w2h, *wgh, *qh, *avgh, *hh, *fh;
    unsigned short *w1x, *w2x, *wgx, *qx, *avgx, *hx, *fx;
    cudaGetSymbolAddress((void**)&w1h, g_W1h);  cudaGetSymbolAddress((void**)&w1x, g_W1x);
    cudaGetSymbolAddress((void**)&w2h, g_W2h);  cudaGetSymbolAddress((void**)&w2x, g_W2x);
    cudaGetSymbolAddress((void**)&wgh, g_Wgh);  cudaGetSymbolAddress((void**)&wgx, g_Wgx);
    cudaGetSymbolAddress((void**)&qh,  g_qh);   cudaGetSymbolAddress((void**)&qx,  g_qx);
    cudaGetSymbolAddress((void**)&avgh, g_avgh); cudaGetSymbolAddress((void**)&avgx, g_avgx);
    cudaGetSymbolAddress((void**)&hh,  g_hh);   cudaGetSymbolAddress((void**)&hx,  g_hx);
    cudaGetSymbolAddress((void**)&fh,  g_fh);   cudaGetSymbolAddress((void**)&fx,  g_fx);

    // operand prep
    k_convert_iQ<<<(M_ * D_ / 32) / 256, 256>>>(iQ);
    k_convert_W<<<dim3(D_ / 64, D_ / 64), 256>>>(W1, w1h, w1x, D_, D_);
    k_convert_W<<<dim3(D_ / 64, D_ / 64), 256>>>(W2, w2h, w2x, D_, D_);
    k_convert_W<<<dim3(2 * D_ / 64, 2 * D_ / 64), 256>>>(Wg, wgh, wgx, 2 * D_, 2 * D_);

    // causal cumulative mean -> (g_avgh, g_avgx)
    k_partial_sums<<<dim3(B_, NCH), D_>>>(iV);
    k_exclusive_prefix<<<B_, D_>>>();
    k_cumavg<<<dim3(B_, NCH), D_>>>(iV);

    // h = relu(avg @ W1 + b1)
    k_gemm_mma<0><<<dim3(D_ / 128, M_ / 128), 256, SMEM_DYN>>>(
        avgh, avgx, nullptr, nullptr, w1h, w1x, b1, D_, nullptr, nullptr);
    // ffn = h @ W2 + b2
    k_gemm_mma<1><<<dim3(D_ / 128, M_ / 128), 256, SMEM_DYN>>>(
        hh, hx, nullptr, nullptr, w2h, w2x, b2, D_, nullptr, nullptr);
    // out = fused gate GEMM + combine (paired cols)
    k_gemm_mma<2><<<dim3(2 * D_ / 128, M_ / 128), 256, SMEM_DYN>>>(
        qh, qx, fh, fx, wgh, wgx, bg, 2 * D_, iQ, out);
}

// round 9
// speedup vs baseline: 1.5752x; 1.5752x over previous
#include <cuda_runtime.h>
#include <cuda_fp16.h>

#define B_   4
#define S_   2048
#define D_   1024
#define M_   (B_ * S_)          // 8192
#define NCH  16
#define CH   (S_ / NCH)         // 128

// ---------------- scratch ----------------------------------------------------
// A-side operands: interleaved fp16 (hi, lo) pairs, K' = 2K slots
// B-side operands: interleaved fp16 (hi, hi) duplicated, K' = 2K slots
__device__ __align__(256) __half g_q2  [(size_t)M_ * 2 * D_];
__device__ __align__(256) __half g_avg2[(size_t)M_ * 2 * D_];
__device__ __align__(256) __half g_h2  [(size_t)M_ * 2 * D_];
__device__ __align__(256) __half g_f2  [(size_t)M_ * 2 * D_];
__device__ __align__(256) __half g_W1d [(size_t)D_ * 2 * D_];        // [N, 2K]
__device__ __align__(256) __half g_W2d [(size_t)D_ * 2 * D_];
__device__ __align__(256) __half g_Wgd [(size_t)2 * D_ * 4 * D_];    // [2048, 4096]
__device__ __align__(256) float g_ffn [(size_t)M_ * D_];
__device__ float g_part[B_ * NCH * D_];

// ---------------- helpers ----------------------------------------------------
__device__ __forceinline__ unsigned smem_u32(const void* p) {
    unsigned r;
    asm("{ .reg .u64 t; cvta.to.shared.u64 t, %1; cvt.u32.u64 %0, t; }" : "=r"(r) : "l"(p));
    return r;
}
// fp16 2-term split packed as u32: slot0 (low half) = hi, slot1 = lo
__device__ __forceinline__ unsigned split_f16(float x) {
    __half h = __float2half_rn(x);
    __half l = __float2half_rn(x - __half2float(h));
    return (unsigned)__half_as_ushort(h) | ((unsigned)__half_as_ushort(l) << 16);
}
// fp16 duplicated pair for B side
__device__ __forceinline__ unsigned dup_f16(float x) {
    unsigned h = (unsigned)__half_as_ushort(__float2half_rn(x));
    return h | (h << 16);
}
__device__ __forceinline__ void ldsm4(unsigned& r0, unsigned& r1, unsigned& r2, unsigned& r3,
                                      unsigned addr) {
    asm volatile("ldmatrix.sync.aligned.m8n8.x4.shared.b16 {%0,%1,%2,%3}, [%4];"
                 : "=r"(r0), "=r"(r1), "=r"(r2), "=r"(r3) : "r"(addr));
}
__device__ __forceinline__ void mma_f16(float* c, unsigned a0, unsigned a1, unsigned a2,
                                        unsigned a3, unsigned b0, unsigned b1) {
    asm volatile(
        "mma.sync.aligned.m16n8k16.row.col.f32.f16.f16.f32 "
        "{%0,%1,%2,%3}, {%4,%5,%6,%7}, {%8,%9}, {%0,%1,%2,%3};"
        : "+f"(c[0]), "+f"(c[1]), "+f"(c[2]), "+f"(c[3])
        : "r"(a0), "r"(a1), "r"(a2), "r"(a3), "r"(b0), "r"(b1));
}

// ---------------- scan: causal cumulative mean -------------------------------
__global__ void k_partial_sums(const float* __restrict__ iV) {
    int b = blockIdx.x, ch = blockIdx.y, d = threadIdx.x;
    const float* p = iV + ((size_t)b * S_ + (size_t)ch * CH) * D_ + d;
    float s = 0.f;
#pragma unroll 8
    for (int t = 0; t < CH; t++) s += p[(size_t)t * D_];
    g_part[(b * NCH + ch) * D_ + d] = s;
}

__global__ void k_exclusive_prefix() {
    int b = blockIdx.x, d = threadIdx.x;
    float run = 0.f;
#pragma unroll
    for (int ch = 0; ch < NCH; ch++) {
        int idx = (b * NCH + ch) * D_ + d;
        float v = g_part[idx];
        g_part[idx] = run;
        run += v;
    }
}

__global__ void k_cumavg(const float* __restrict__ iV) {
    int b = blockIdx.x, ch = blockIdx.y, d = threadIdx.x;
    float run = g_part[(b * NCH + ch) * D_ + d];
    const float* p = iV + ((size_t)b * S_ + (size_t)ch * CH) * D_ + d;
    size_t mrow = (size_t)b * S_ + (size_t)ch * CH;
#pragma unroll 4
    for (int t = 0; t < CH; t++) {
        run += p[(size_t)t * D_];
        int s = ch * CH + t;
        float x = run * (1.0f / (float)(s + 1));
        *(unsigned*)(g_avg2 + (mrow + t) * (2 * D_) + 2 * d) = split_f16(x);
    }
}

// ---------------- conversions ------------------------------------------------
// iQ fp32 -> g_q2 (hi, lo) fp16 pairs, 32 elements per thread
__global__ __launch_bounds__(256) void k_convert_iQ(const float* __restrict__ iQ) {
    size_t t = (size_t)blockIdx.x * blockDim.x + threadIdx.x;   // M_*D_/32 threads
    size_t m  = t / (D_ / 32);
    int    dq = (int)(t % (D_ / 32)) * 32;
    const float4* src = (const float4*)(iQ + m * D_ + dq);
    unsigned w[32];
#pragma unroll
    for (int i = 0; i < 8; i++) {
        float4 x = src[i];
        w[4 * i + 0] = split_f16(x.x);
        w[4 * i + 1] = split_f16(x.y);
        w[4 * i + 2] = split_f16(x.z);
        w[4 * i + 3] = split_f16(x.w);
    }
    uint4* dst = (uint4*)(g_q2 + m * (2 * D_) + 2 * dq);
#pragma unroll
    for (int i = 0; i < 8; i++)
        dst[i] = make_uint4(w[4 * i], w[4 * i + 1], w[4 * i + 2], w[4 * i + 3]);
}

// W [K,N] fp32 -> Wd [N, 2K] fp16 (hi, hi) duplicated, via smem transpose
__global__ __launch_bounds__(256) void k_convert_W(const float* __restrict__ W,
                                                   __half* __restrict__ Wd,
                                                   int K, int N) {
    __shared__ float t[64][65];
    const int tid = threadIdx.x;
    const int n0 = blockIdx.x * 64, k0 = blockIdx.y * 64;
    {
        const int r = tid >> 4;
        const int c4 = tid & 15;
#pragma unroll
        for (int i = 0; i < 4; i++) {
            int k = r + 16 * i;
            float4 v = *(const float4*)(W + (size_t)(k0 + k) * N + n0 + 4 * c4);
            t[k][4 * c4 + 0] = v.x;
            t[k][4 * c4 + 1] = v.y;
            t[k][4 * c4 + 2] = v.z;
            t[k][4 * c4 + 3] = v.w;
        }
    }
    __syncthreads();
    const int n = tid >> 2;
    const int kq = tid & 3;              // 16 orig-k each
    unsigned w[16];
#pragma unroll
    for (int j = 0; j < 16; j++)
        w[j] = dup_f16(t[16 * kq + j][n]);
    uint4* dst = (uint4*)(Wd + (size_t)(n0 + n) * (2 * K) + 2 * (k0 + 16 * kq));
#pragma unroll
    for (int i = 0; i < 4; i++)
        dst[i] = make_uint4(w[4 * i], w[4 * i + 1], w[4 * i + 2], w[4 * i + 3]);
}

// ---------------- fp16 2-slot GEMM (128x256 tile, 512 threads) -----------------
// SEL 0: avg2 @ W1d -> relu+b1 -> g_h2
// SEL 1: h2   @ W2d -> +b2    -> g_ffn fp32 + g_f2
// SEL 2: concat(q2, f2) @ Wgd (paired cols n, n+1024) -> sigmoid ->
//        smem exchange -> out = igate*iQ + fgate*ffn
#define BM 128
#define BN 256
#define BK 64            // fp16 slots per K block = 128 B row = 32 orig-k
#define STAGES 3
#define A_BYTES (BM * 128)                  // 16 KB
#define B_BYTES (BN * 128)                  // 32 KB
#define STG_BYTES (A_BYTES + B_BYTES)       // 48 KB
#define SMEM_DYN (STAGES * STG_BYTES)       // 144 KB

template <int SEL>
__global__ __launch_bounds__(512, 1)
void k_gemm_mma(const __half* __restrict__ A0,
                const __half* __restrict__ A1,
                const __half* __restrict__ Bw,
                const float* __restrict__ bias,
                int K2,                       // slots per B row (2K)
                const float* __restrict__ iQf,
                float* __restrict__ out)
{
    extern __shared__ __align__(1024) char dsmem[];
    const unsigned sbase = smem_u32(dsmem);

    const int tid = threadIdx.x;
    const int warp = tid >> 5, lid = tid & 31;
    const int wm = warp >> 3;            // 0..1  -> 64 rows each
    const int wn = warp & 7;             // 0..7  -> 32 cols each
    const int m0 = blockIdx.y * BM;
    const int n0 = blockIdx.x * BN;      // SEL0/1 col base
    const int cg0 = blockIdx.x * 128;    // SEL2: gate col-pair base
    const int NB = K2 / BK;

    const int ar  = tid >> 2;            // 0..127
    const int ac0 = (tid & 3) * 2;
    const int br  = tid >> 1;            // 0..255
    const int bc0 = (tid & 1) * 4;

    float acc[4][4][4];
#pragma unroll
    for (int i = 0; i < 4; i++)
#pragma unroll
        for (int j = 0; j < 4; j++)
#pragma unroll
            for (int k = 0; k < 4; k++) acc[i][j][k] = 0.f;

    auto load_blk = [&](int kb, int stage) {
        unsigned sA = sbase + stage * STG_BYTES;
        unsigned sB = sA + A_BYTES;
        const __half* Arow;
        if (SEL == 2 && kb >= 32)
            Arow = A1 + (size_t)(m0 + ar) * (2 * D_) + (size_t)(kb - 32) * BK;
        else
            Arow = A0 + (size_t)(m0 + ar) * (2 * D_) + (size_t)kb * BK;
        unsigned long long ag = (unsigned long long)Arow;
        unsigned asm_ = sA + ar * 128;
        const int aswz = ar & 7;
#pragma unroll
        for (int i = 0; i < 2; i++) {
            int c = ac0 + i;
            asm volatile("cp.async.cg.shared.global [%0], [%1], 16;"
                         :: "r"(asm_ + (unsigned)((c ^ aswz) << 4)), "l"(ag + c * 16) : "memory");
        }
        int gn;
        if (SEL == 2) gn = (br < 128) ? (cg0 + br) : (1024 + cg0 + br - 128);
        else          gn = n0 + br;
        const __half* Brow = Bw + (size_t)gn * K2 + (size_t)kb * BK;
        unsigned long long bg2 = (unsigned long long)Brow;
        unsigned bsm = sB + br * 128;
        const int bswz = br & 7;
#pragma unroll
        for (int i = 0; i < 4; i++) {
            int c = bc0 + i;
            asm volatile("cp.async.cg.shared.global [%0], [%1], 16;"
                         :: "r"(bsm + (unsigned)((c ^ bswz) << 4)), "l"(bg2 + c * 16) : "memory");
        }
        asm volatile("cp.async.commit_group;" ::: "memory");
    };

    // ---- fragment addressing ----
    int arow[4], brow[2];
#pragma unroll
    for (int mt = 0; mt < 4; mt++)
        arow[mt] = wm * 64 + mt * 16 + (lid & 7) + ((lid >> 3) & 1) * 8;
    const int ahi = lid >> 4;
#pragma unroll
    for (int p = 0; p < 2; p++)
        brow[p] = wn * 32 + p * 16 + (lid & 7) + (lid >> 4) * 8;
    const int bhi = (lid >> 3) & 1;

    // ---- prologue ----
#pragma unroll
    for (int s = 0; s < STAGES - 1; s++) load_blk(s, s);

    for (int kb = 0; kb < NB; kb++) {
        asm volatile("cp.async.wait_group %0;" :: "n"(STAGES - 2) : "memory");
        __syncthreads();
        if (kb + STAGES - 1 < NB) load_blk(kb + STAGES - 1, (kb + STAGES - 1) % STAGES);

        unsigned sA = sbase + (kb % STAGES) * STG_BYTES;
        unsigned sB = sA + A_BYTES;
#pragma unroll
        for (int ks = 0; ks < 4; ks++) {
            unsigned a[4][4];
#pragma unroll
            for (int mt = 0; mt < 4; mt++) {
                unsigned addr = sA + arow[mt] * 128 +
                                (unsigned)(((2 * ks + ahi) ^ (arow[mt] & 7)) << 4);
                ldsm4(a[mt][0], a[mt][1], a[mt][2], a[mt][3], addr);
            }
            unsigned b[2][4];
#pragma unroll
            for (int p = 0; p < 2; p++) {
                unsigned addr = sB + brow[p] * 128 +
                                (unsigned)(((2 * ks + bhi) ^ (brow[p] & 7)) << 4);
                ldsm4(b[p][0], b[p][1], b[p][2], b[p][3], addr);
            }
#pragma unroll
            for (int mt = 0; mt < 4; mt++)
#pragma unroll
                for (int nt = 0; nt < 4; nt++)
                    mma_f16(acc[mt][nt], a[mt][0], a[mt][1], a[mt][2], a[mt][3],
                            b[nt >> 1][(nt & 1) * 2], b[nt >> 1][(nt & 1) * 2 + 1]);
        }
    }

    // ---- epilogue ----
    const int gid = lid >> 2, tig = lid & 3;

    if (SEL == 2) {
        __syncthreads();
        float* gsm = (float*)dsmem;        // [128][260]
#pragma unroll
        for (int mt = 0; mt < 4; mt++) {
#pragma unroll
            for (int r2 = 0; r2 < 2; r2++) {
                const int ml = wm * 64 + mt * 16 + gid + r2 * 8;
#pragma unroll
                for (int nt = 0; nt < 4; nt++) {
                    const int nl = wn * 32 + nt * 8 + 2 * tig;
                    const int gcol = (nl < 128) ? (cg0 + nl) : (1024 + cg0 + nl - 128);
                    float2 bb = *(const float2*)(bias + gcol);
                    float v0 = acc[mt][nt][r2 * 2 + 0] + bb.x;
                    float v1 = acc[mt][nt][r2 * 2 + 1] + bb.y;
                    v0 = 1.0f / (1.0f + __expf(-v0));
                    v1 = 1.0f / (1.0f + __expf(-v1));
                    gsm[ml * 260 + nl]     = v0;
                    gsm[ml * 260 + nl + 1] = v1;
                }
            }
        }
        __syncthreads();
        const int c4 = tid & 31;            // float4 col group 0..31
        const int r0 = tid >> 5;            // 0..15
#pragma unroll
        for (int i = 0; i < 8; i++) {
            const int r = r0 + 16 * i;
            const int col = 4 * c4;
            const size_t gidx = (size_t)(m0 + r) * D_ + cg0 + col;
            float4 q = *(const float4*)(iQf + gidx);
            float4 f = *(const float4*)(g_ffn + gidx);
            float4 gi = *(const float4*)&gsm[r * 260 + col];
            float4 gf = *(const float4*)&gsm[r * 260 + 128 + col];
            float4 o;
            o.x = gi.x * q.x + gf.x * f.x;
            o.y = gi.y * q.y + gf.y * f.y;
            o.z = gi.z * q.z + gf.z * f.z;
            o.w = gi.w * q.w + gf.w * f.w;
            *(float4*)(out + gidx) = o;
        }
        return;
    }

#pragma unroll
    for (int mt = 0; mt < 4; mt++) {
#pragma unroll
        for (int r2 = 0; r2 < 2; r2++) {
            const int m = m0 + wm * 64 + mt * 16 + gid + r2 * 8;
#pragma unroll
            for (int nt = 0; nt < 4; nt++) {
                const int n = n0 + wn * 32 + nt * 8 + 2 * tig;     // even
                float2 bb = *(const float2*)(bias + n);
                float v0 = acc[mt][nt][r2 * 2 + 0] + bb.x;
                float v1 = acc[mt][nt][r2 * 2 + 1] + bb.y;
                if (SEL == 0) {
                    v0 = fmaxf(v0, 0.f); v1 = fmaxf(v1, 0.f);
                    *(uint2*)(g_h2 + (size_t)m * (2 * D_) + 2 * n) =
                        make_uint2(split_f16(v0), split_f16(v1));
                } else {
                    *(float2*)(g_ffn + (size_t)m * D_ + n) = make_float2(v0, v1);
                    *(uint2*)(g_f2 + (size_t)m * (2 * D_) + 2 * n) =
                        make_uint2(split_f16(v0), split_f16(v1));
                }
            }
        }
    }
}

// ---------------- launch ------------------------------------------------------
extern "C" void kernel_launch(void* const* d_in, const int* in_sizes, int n_in,
                              void* d_out, int out_size) {
    const float* iQ = (const float*)d_in[0];
    const float* iV = (const float*)d_in[1];
    const float* W1 = (const float*)d_in[2];
    const float* b1 = (const float*)d_in[3];
    const float* W2 = (const float*)d_in[4];
    const float* b2 = (const float*)d_in[5];
    const float* Wg = (const float*)d_in[6];
    const float* bg = (const float*)d_in[7];
    float* out = (float*)d_out;

    cudaFuncSetAttribute(k_gemm_mma<0>, cudaFuncAttributeMaxDynamicSharedMemorySize, SMEM_DYN);
    cudaFuncSetAttribute(k_gemm_mma<1>, cudaFuncAttributeMaxDynamicSharedMemorySize, SMEM_DYN);
    cudaFuncSetAttribute(k_gemm_mma<2>, cudaFuncAttributeMaxDynamicSharedMemorySize, SMEM_DYN);

    __half *w1d, *w2d, *wgd, *q2, *avg2, *h2, *f2;
    cudaGetSymbolAddress((void**)&w1d, g_W1d);
    cudaGetSymbolAddress((void**)&w2d, g_W2d);
    cudaGetSymbolAddress((void**)&wgd, g_Wgd);
    cudaGetSymbolAddress((void**)&q2,  g_q2);
    cudaGetSymbolAddress((void**)&avg2, g_avg2);
    cudaGetSymbolAddress((void**)&h2,  g_h2);
    cudaGetSymbolAddress((void**)&f2,  g_f2);

    // operand prep
    k_convert_iQ<<<(M_ * D_ / 32) / 256, 256>>>(iQ);
    k_convert_W<<<dim3(D_ / 64, D_ / 64), 256>>>(W1, w1d, D_, D_);
    k_convert_W<<<dim3(D_ / 64, D_ / 64), 256>>>(W2, w2d, D_, D_);
    k_convert_W<<<dim3(2 * D_ / 64, 2 * D_ / 64), 256>>>(Wg, wgd, 2 * D_, 2 * D_);

    // causal cumulative mean -> g_avg2
    k_partial_sums<<<dim3(B_, NCH), D_>>>(iV);
    k_exclusive_prefix<<<B_, D_>>>();
    k_cumavg<<<dim3(B_, NCH), D_>>>(iV);

    // h = relu(avg @ W1 + b1)            [K'=2048 slots]
    k_gemm_mma<0><<<dim3(D_ / BN, M_ / BM), 512, SMEM_DYN>>>(
        avg2, nullptr, w1d, b1, 2 * D_, nullptr, nullptr);
    // ffn = h @ W2 + b2                  [K'=2048 slots]
    k_gemm_mma<1><<<dim3(D_ / BN, M_ / BM), 512, SMEM_DYN>>>(
        h2, nullptr, w2d, b2, 2 * D_, nullptr, nullptr);
    // out = fused gate GEMM + combine    [K'=4096 slots, paired cols]
    k_gemm_mma<2><<<dim3(2 * D_ / BN, M_ / BM), 512, SMEM_DYN>>>(
        q2, f2, wgd, bg, 4 * D_, iQ, out);
}

// round 11
// speedup vs baseline: 2.7724x; 1.7600x over previous
#include <cuda_runtime.h>
#include <cuda_fp16.h>

#define B_   4
#define S_   2048
#define D_   1024
#define M_   (B_ * S_)          // 8192
#define NCH  16
#define CH   (S_ / NCH)         // 128

// ---------------- scratch ----------------------------------------------------
// plain fp16 operands, K-major
__device__ __align__(256) __half g_q  [(size_t)M_ * D_];
__device__ __align__(256) __half g_avg[(size_t)M_ * D_];
__device__ __align__(256) __half g_h  [(size_t)M_ * D_];
__device__ __align__(256) __half g_f  [(size_t)M_ * D_];
__device__ __align__(256) __half g_W1t[(size_t)D_ * D_];        // [N, K]
__device__ __align__(256) __half g_W2t[(size_t)D_ * D_];
__device__ __align__(256) __half g_Wgt[(size_t)2 * D_ * 2 * D_];
__device__ __align__(256) float g_ffn [(size_t)M_ * D_];
__device__ float g_part[B_ * NCH * D_];

// ---------------- helpers ----------------------------------------------------
__device__ __forceinline__ unsigned smem_u32(const void* p) {
    unsigned r;
    asm("{ .reg .u64 t; cvta.to.shared.u64 t, %1; cvt.u32.u64 %0, t; }" : "=r"(r) : "l"(p));
    return r;
}
__device__ __forceinline__ unsigned pk_f16(float a, float b) {
    return (unsigned)__half_as_ushort(__float2half_rn(a)) |
           ((unsigned)__half_as_ushort(__float2half_rn(b)) << 16);
}
__device__ __forceinline__ void ldsm4(unsigned& r0, unsigned& r1, unsigned& r2, unsigned& r3,
                                      unsigned addr) {
    asm volatile("ldmatrix.sync.aligned.m8n8.x4.shared.b16 {%0,%1,%2,%3}, [%4];"
                 : "=r"(r0), "=r"(r1), "=r"(r2), "=r"(r3) : "r"(addr));
}
__device__ __forceinline__ void mma_f16(float* c, unsigned a0, unsigned a1, unsigned a2,
                                        unsigned a3, unsigned b0, unsigned b1) {
    asm volatile(
        "mma.sync.aligned.m16n8k16.row.col.f32.f16.f16.f32 "
        "{%0,%1,%2,%3}, {%4,%5,%6,%7}, {%8,%9}, {%0,%1,%2,%3};"
        : "+f"(c[0]), "+f"(c[1]), "+f"(c[2]), "+f"(c[3])
        : "r"(a0), "r"(a1), "r"(a2), "r"(a3), "r"(b0), "r"(b1));
}

// ---------------- scan: causal cumulative mean -------------------------------
__global__ void k_partial_sums(const float* __restrict__ iV) {
    int b = blockIdx.x, ch = blockIdx.y, d = threadIdx.x;
    const float* p = iV + ((size_t)b * S_ + (size_t)ch * CH) * D_ + d;
    float s = 0.f;
#pragma unroll 8
    for (int t = 0; t < CH; t++) s += p[(size_t)t * D_];
    g_part[(b * NCH + ch) * D_ + d] = s;
}

__global__ void k_exclusive_prefix() {
    int b = blockIdx.x, d = threadIdx.x;
    float run = 0.f;
#pragma unroll
    for (int ch = 0; ch < NCH; ch++) {
        int idx = (b * NCH + ch) * D_ + d;
        float v = g_part[idx];
        g_part[idx] = run;
        run += v;
    }
}

__global__ void k_cumavg(const float* __restrict__ iV) {
    int b = blockIdx.x, ch = blockIdx.y, d = threadIdx.x;
    float run = g_part[(b * NCH + ch) * D_ + d];
    const float* p = iV + ((size_t)b * S_ + (size_t)ch * CH) * D_ + d;
    size_t mrow = (size_t)b * S_ + (size_t)ch * CH;
#pragma unroll 4
    for (int t = 0; t < CH; t++) {
        run += p[(size_t)t * D_];
        int s = ch * CH + t;
        float x = run * (1.0f / (float)(s + 1));
        g_avg[(mrow + t) * D_ + d] = __float2half_rn(x);
    }
}

// ---------------- conversions ------------------------------------------------
// iQ fp32 -> g_q fp16, 32 elements per thread
__global__ __launch_bounds__(256) void k_convert_iQ(const float* __restrict__ iQ) {
    size_t t = (size_t)blockIdx.x * blockDim.x + threadIdx.x;   // M_*D_/32 threads
    size_t m  = t / (D_ / 32);
    int    dq = (int)(t % (D_ / 32)) * 32;
    const float4* src = (const float4*)(iQ + m * D_ + dq);
    unsigned w[16];
#pragma unroll
    for (int i = 0; i < 8; i++) {
        float4 x = src[i];
        w[2 * i]     = pk_f16(x.x, x.y);
        w[2 * i + 1] = pk_f16(x.z, x.w);
    }
    uint4* dst = (uint4*)(g_q + m * D_ + dq);
#pragma unroll
    for (int i = 0; i < 4; i++)
        dst[i] = make_uint4(w[4 * i], w[4 * i + 1], w[4 * i + 2], w[4 * i + 3]);
}

// W [K,N] fp32 -> Wt [N, K] fp16, via smem transpose
__global__ __launch_bounds__(256) void k_convert_W(const float* __restrict__ W,
                                                   __half* __restrict__ Wt,
                                                   int K, int N) {
    __shared__ float t[64][65];
    const int tid = threadIdx.x;
    const int n0 = blockIdx.x * 64, k0 = blockIdx.y * 64;
    {
        const int r = tid >> 4;
        const int c4 = tid & 15;
#pragma unroll
        for (int i = 0; i < 4; i++) {
            int k = r + 16 * i;
            float4 v = *(const float4*)(W + (size_t)(k0 + k) * N + n0 + 4 * c4);
            t[k][4 * c4 + 0] = v.x;
            t[k][4 * c4 + 1] = v.y;
            t[k][4 * c4 + 2] = v.z;
            t[k][4 * c4 + 3] = v.w;
        }
    }
    __syncthreads();
    const int n = tid >> 2;
    const int kq = tid & 3;              // 16 orig-k each
    unsigned w[8];
#pragma unroll
    for (int j = 0; j < 8; j++)
        w[j] = pk_f16(t[16 * kq + 2 * j][n], t[16 * kq + 2 * j + 1][n]);
    uint4* dst = (uint4*)(Wt + (size_t)(n0 + n) * K + k0 + 16 * kq);
    dst[0] = make_uint4(w[0], w[1], w[2], w[3]);
    dst[1] = make_uint4(w[4], w[5], w[6], w[7]);
}

// ---------------- fp16 GEMM (128x256 tile, 512 threads) ------------------------
// SEL 0: avg @ W1t -> relu+b1 -> g_h
// SEL 1: h   @ W2t -> +b2    -> g_ffn fp32 + g_f
// SEL 2: concat(q, f) @ Wgt (paired cols n, n+1024) -> sigmoid ->
//        smem exchange -> out = igate*iQ + fgate*ffn
#define BM 128
#define BN 256
#define BK 64            // fp16 per K block = 128 B row
#define STAGES 3
#define A_BYTES (BM * 128)                  // 16 KB
#define B_BYTES (BN * 128)                  // 32 KB
#define STG_BYTES (A_BYTES + B_BYTES)       // 48 KB
#define SMEM_DYN (STAGES * STG_BYTES)       // 144 KB

template <int SEL>
__global__ __launch_bounds__(512, 1)
void k_gemm_mma(const __half* __restrict__ A0,
                const __half* __restrict__ A1,
                const __half* __restrict__ Bw,
                const float* __restrict__ bias,
                int K,                        // B row length (orig K)
                const float* __restrict__ iQf,
                float* __restrict__ out)
{
    extern __shared__ __align__(1024) char dsmem[];
    const unsigned sbase = smem_u32(dsmem);

    const int tid = threadIdx.x;
    const int warp = tid >> 5, lid = tid & 31;
    const int wm = warp >> 3;            // 0..1  -> 64 rows each
    const int wn = warp & 7;             // 0..7  -> 32 cols each
    const int m0 = blockIdx.y * BM;
    const int n0 = blockIdx.x * BN;      // SEL0/1 col base
    const int cg0 = blockIdx.x * 128;    // SEL2: gate col-pair base
    const int NB = K / BK;

    const int ar  = tid >> 2;            // 0..127
    const int ac0 = (tid & 3) * 2;
    const int br  = tid >> 1;            // 0..255
    const int bc0 = (tid & 1) * 4;

    float acc[4][4][4];
#pragma unroll
    for (int i = 0; i < 4; i++)
#pragma unroll
        for (int j = 0; j < 4; j++)
#pragma unroll
            for (int k = 0; k < 4; k++) acc[i][j][k] = 0.f;

    auto load_blk = [&](int kb, int stage) {
        unsigned sA = sbase + stage * STG_BYTES;
        unsigned sB = sA + A_BYTES;
        const __half* Arow;
        if (SEL == 2 && kb >= 16)
            Arow = A1 + (size_t)(m0 + ar) * D_ + (size_t)(kb - 16) * BK;
        else
            Arow = A0 + (size_t)(m0 + ar) * D_ + (size_t)kb * BK;
        unsigned long long ag = (unsigned long long)Arow;
        unsigned asm_ = sA + ar * 128;
        const int aswz = ar & 7;
#pragma unroll
        for (int i = 0; i < 2; i++) {
            int c = ac0 + i;
            asm volatile("cp.async.cg.shared.global [%0], [%1], 16;"
                         :: "r"(asm_ + (unsigned)((c ^ aswz) << 4)), "l"(ag + c * 16) : "memory");
        }
        int gn;
        if (SEL == 2) gn = (br < 128) ? (cg0 + br) : (1024 + cg0 + br - 128);
        else          gn = n0 + br;
        const __half* Brow = Bw + (size_t)gn * K + (size_t)kb * BK;
        unsigned long long bg2 = (unsigned long long)Brow;
        unsigned bsm = sB + br * 128;
        const int bswz = br & 7;
#pragma unroll
        for (int i = 0; i < 4; i++) {
            int c = bc0 + i;
            asm volatile("cp.async.cg.shared.global [%0], [%1], 16;"
                         :: "r"(bsm + (unsigned)((c ^ bswz) << 4)), "l"(bg2 + c * 16) : "memory");
        }
        asm volatile("cp.async.commit_group;" ::: "memory");
    };

    // ---- fragment addressing ----
    int arow[4], brow[2];
#pragma unroll
    for (int mt = 0; mt < 4; mt++)
        arow[mt] = wm * 64 + mt * 16 + (lid & 7) + ((lid >> 3) & 1) * 8;
    const int ahi = lid >> 4;
#pragma unroll
    for (int p = 0; p < 2; p++)
        brow[p] = wn * 32 + p * 16 + (lid & 7) + (lid >> 4) * 8;
    const int bhi = (lid >> 3) & 1;

    // ---- prologue ----
#pragma unroll
    for (int s = 0; s < STAGES - 1; s++) load_blk(s, s);

    for (int kb = 0; kb < NB; kb++) {
        asm volatile("cp.async.wait_group %0;" :: "n"(STAGES - 2) : "memory");
        __syncthreads();
        if (kb + STAGES - 1 < NB) load_blk(kb + STAGES - 1, (kb + STAGES - 1) % STAGES);

        unsigned sA = sbase + (kb % STAGES) * STG_BYTES;
        unsigned sB = sA + A_BYTES;
#pragma unroll
        for (int ks = 0; ks < 4; ks++) {
            unsigned a[4][4];
#pragma unroll
            for (int mt = 0; mt < 4; mt++) {
                unsigned addr = sA + arow[mt] * 128 +
                                (unsigned)(((2 * ks + ahi) ^ (arow[mt] & 7)) << 4);
                ldsm4(a[mt][0], a[mt][1], a[mt][2], a[mt][3], addr);
            }
            unsigned b[2][4];
#pragma unroll
            for (int p = 0; p < 2; p++) {
                unsigned addr = sB + brow[p] * 128 +
                                (unsigned)(((2 * ks + bhi) ^ (brow[p] & 7)) << 4);
                ldsm4(b[p][0], b[p][1], b[p][2], b[p][3], addr);
            }
#pragma unroll
            for (int mt = 0; mt < 4; mt++)
#pragma unroll
                for (int nt = 0; nt < 4; nt++)
                    mma_f16(acc[mt][nt], a[mt][0], a[mt][1], a[mt][2], a[mt][3],
                            b[nt >> 1][(nt & 1) * 2], b[nt >> 1][(nt & 1) * 2 + 1]);
        }
    }

    // ---- epilogue ----
    const int gid = lid >> 2, tig = lid & 3;

    if (SEL == 2) {
        __syncthreads();
        float* gsm = (float*)dsmem;        // [128][260]
#pragma unroll
        for (int mt = 0; mt < 4; mt++) {
#pragma unroll
            for (int r2 = 0; r2 < 2; r2++) {
                const int ml = wm * 64 + mt * 16 + gid + r2 * 8;
#pragma unroll
                for (int nt = 0; nt < 4; nt++) {
                    const int nl = wn * 32 + nt * 8 + 2 * tig;
                    const int gcol = (nl < 128) ? (cg0 + nl) : (1024 + cg0 + nl - 128);
                    float2 bb = *(const float2*)(bias + gcol);
                    float v0 = acc[mt][nt][r2 * 2 + 0] + bb.x;
                    float v1 = acc[mt][nt][r2 * 2 + 1] + bb.y;
                    v0 = 1.0f / (1.0f + __expf(-v0));
                    v1 = 1.0f / (1.0f + __expf(-v1));
                    gsm[ml * 260 + nl]     = v0;
                    gsm[ml * 260 + nl + 1] = v1;
                }
            }
        }
        __syncthreads();
        const int c4 = tid & 31;            // float4 col group 0..31
        const int r0 = tid >> 5;            // 0..15
#pragma unroll
        for (int i = 0; i < 8; i++) {
            const int r = r0 + 16 * i;
            const int col = 4 * c4;
            const size_t gidx = (size_t)(m0 + r) * D_ + cg0 + col;
            float4 q = *(const float4*)(iQf + gidx);
            float4 f = *(const float4*)(g_ffn + gidx);
            float4 gi = *(const float4*)&gsm[r * 260 + col];
            float4 gf = *(const float4*)&gsm[r * 260 + 128 + col];
            float4 o;
            o.x = gi.x * q.x + gf.x * f.x;
            o.y = gi.y * q.y + gf.y * f.y;
            o.z = gi.z * q.z + gf.z * f.z;
            o.w = gi.w * q.w + gf.w * f.w;
            *(float4*)(out + gidx) = o;
        }
        return;
    }

#pragma unroll
    for (int mt = 0; mt < 4; mt++) {
#pragma unroll
        for (int r2 = 0; r2 < 2; r2++) {
            const int m = m0 + wm * 64 + mt * 16 + gid + r2 * 8;
#pragma unroll
            for (int nt = 0; nt < 4; nt++) {
                const int n = n0 + wn * 32 + nt * 8 + 2 * tig;     // even
                float2 bb = *(const float2*)(bias + n);
                float v0 = acc[mt][nt][r2 * 2 + 0] + bb.x;
                float v1 = acc[mt][nt][r2 * 2 + 1] + bb.y;
                if (SEL == 0) {
                    v0 = fmaxf(v0, 0.f); v1 = fmaxf(v1, 0.f);
                    *(unsigned*)(g_h + (size_t)m * D_ + n) = pk_f16(v0, v1);
                } else {
                    *(float2*)(g_ffn + (size_t)m * D_ + n) = make_float2(v0, v1);
                    *(unsigned*)(g_f + (size_t)m * D_ + n) = pk_f16(v0, v1);
                }
            }
        }
    }
}

// ---------------- launch ------------------------------------------------------
extern "C" void kernel_launch(void* const* d_in, const int* in_sizes, int n_in,
                              void* d_out, int out_size) {
    const float* iQ = (const float*)d_in[0];
    const float* iV = (const float*)d_in[1];
    const float* W1 = (const float*)d_in[2];
    const float* b1 = (const float*)d_in[3];
    const float* W2 = (const float*)d_in[4];
    const float* b2 = (const float*)d_in[5];
    const float* Wg = (const float*)d_in[6];
    const float* bg = (const float*)d_in[7];
    float* out = (float*)d_out;

    cudaFuncSetAttribute(k_gemm_mma<0>, cudaFuncAttributeMaxDynamicSharedMemorySize, SMEM_DYN);
    cudaFuncSetAttribute(k_gemm_mma<1>, cudaFuncAttributeMaxDynamicSharedMemorySize, SMEM_DYN);
    cudaFuncSetAttribute(k_gemm_mma<2>, cudaFuncAttributeMaxDynamicSharedMemorySize, SMEM_DYN);

    __half *w1t, *w2t, *wgt, *q, *avg, *h, *f;
    cudaGetSymbolAddress((void**)&w1t, g_W1t);
    cudaGetSymbolAddress((void**)&w2t, g_W2t);
    cudaGetSymbolAddress((void**)&wgt, g_Wgt);
    cudaGetSymbolAddress((void**)&q,   g_q);
    cudaGetSymbolAddress((void**)&avg, g_avg);
    cudaGetSymbolAddress((void**)&h,   g_h);
    cudaGetSymbolAddress((void**)&f,   g_f);

    // operand prep
    k_convert_iQ<<<(M_ * D_ / 32) / 256, 256>>>(iQ);
    k_convert_W<<<dim3(D_ / 64, D_ / 64), 256>>>(W1, w1t, D_, D_);
    k_convert_W<<<dim3(D_ / 64, D_ / 64), 256>>>(W2, w2t, D_, D_);
    k_convert_W<<<dim3(2 * D_ / 64, 2 * D_ / 64), 256>>>(Wg, wgt, 2 * D_, 2 * D_);

    // causal cumulative mean -> g_avg
    k_partial_sums<<<dim3(B_, NCH), D_>>>(iV);
    k_exclusive_prefix<<<B_, D_>>>();
    k_cumavg<<<dim3(B_, NCH), D_>>>(iV);

    // h = relu(avg @ W1 + b1)            [K=1024]
    k_gemm_mma<0><<<dim3(D_ / BN, M_ / BM), 512, SMEM_DYN>>>(
        avg, nullptr, w1t, b1, D_, nullptr, nullptr);
    // ffn = h @ W2 + b2                  [K=1024]
    k_gemm_mma<1><<<dim3(D_ / BN, M_ / BM), 512, SMEM_DYN>>>(
        h, nullptr, w2t, b2, D_, nullptr, nullptr);
    // out = fused gate GEMM + combine    [K=2048, paired cols]
    k_gemm_mma<2><<<dim3(2 * D_ / BN, M_ / BM), 512, SMEM_DYN>>>(
        q, f, wgt, bg, 2 * D_, iQ, out);
}

// round 12
// speedup vs baseline: 2.8162x; 1.0158x over previous
#include <cuda_runtime.h>
#include <cuda_fp16.h>

#define B_   4
#define S_   2048
#define D_   1024
#define M_   (B_ * S_)          // 8192
#define NCH  16
#define CH   (S_ / NCH)         // 128

// ---------------- scratch ----------------------------------------------------
// plain fp16 operands, K-major
__device__ __align__(256) __half g_q  [(size_t)M_ * D_];
__device__ __align__(256) __half g_avg[(size_t)M_ * D_];
__device__ __align__(256) __half g_h  [(size_t)M_ * D_];
__device__ __align__(256) __half g_f  [(size_t)M_ * D_];
__device__ __align__(256) __half g_W1t[(size_t)D_ * D_];        // [N, K]
__device__ __align__(256) __half g_W2t[(size_t)D_ * D_];
__device__ __align__(256) __half g_Wgt[(size_t)2 * D_ * 2 * D_];
__device__ float g_part[B_ * NCH * D_];

// ---------------- helpers ----------------------------------------------------
__device__ __forceinline__ unsigned smem_u32(const void* p) {
    unsigned r;
    asm("{ .reg .u64 t; cvta.to.shared.u64 t, %1; cvt.u32.u64 %0, t; }" : "=r"(r) : "l"(p));
    return r;
}
__device__ __forceinline__ unsigned pk_f16(float a, float b) {
    return (unsigned)__half_as_ushort(__float2half_rn(a)) |
           ((unsigned)__half_as_ushort(__float2half_rn(b)) << 16);
}
__device__ __forceinline__ void ldsm4(unsigned& r0, unsigned& r1, unsigned& r2, unsigned& r3,
                                      unsigned addr) {
    asm volatile("ldmatrix.sync.aligned.m8n8.x4.shared.b16 {%0,%1,%2,%3}, [%4];"
                 : "=r"(r0), "=r"(r1), "=r"(r2), "=r"(r3) : "r"(addr));
}
__device__ __forceinline__ void mma_f16(float* c, unsigned a0, unsigned a1, unsigned a2,
                                        unsigned a3, unsigned b0, unsigned b1) {
    asm volatile(
        "mma.sync.aligned.m16n8k16.row.col.f32.f16.f16.f32 "
        "{%0,%1,%2,%3}, {%4,%5,%6,%7}, {%8,%9}, {%0,%1,%2,%3};"
        : "+f"(c[0]), "+f"(c[1]), "+f"(c[2]), "+f"(c[3])
        : "r"(a0), "r"(a1), "r"(a2), "r"(a3), "r"(b0), "r"(b1));
}

// ---------------- scan: causal cumulative mean -------------------------------
__global__ void k_partial_sums(const float* __restrict__ iV) {
    int b = blockIdx.x, ch = blockIdx.y, d = threadIdx.x;
    const float* p = iV + ((size_t)b * S_ + (size_t)ch * CH) * D_ + d;
    float s = 0.f;
#pragma unroll 8
    for (int t = 0; t < CH; t++) s += p[(size_t)t * D_];
    g_part[(b * NCH + ch) * D_ + d] = s;
}

__global__ void k_exclusive_prefix() {
    int b = blockIdx.x, d = threadIdx.x;
    float run = 0.f;
#pragma unroll
    for (int ch = 0; ch < NCH; ch++) {
        int idx = (b * NCH + ch) * D_ + d;
        float v = g_part[idx];
        g_part[idx] = run;
        run += v;
    }
}

__global__ void k_cumavg(const float* __restrict__ iV) {
    int b = blockIdx.x, ch = blockIdx.y, d = threadIdx.x;
    float run = g_part[(b * NCH + ch) * D_ + d];
    const float* p = iV + ((size_t)b * S_ + (size_t)ch * CH) * D_ + d;
    size_t mrow = (size_t)b * S_ + (size_t)ch * CH;
#pragma unroll 4
    for (int t = 0; t < CH; t++) {
        run += p[(size_t)t * D_];
        int s = ch * CH + t;
        float x = run * (1.0f / (float)(s + 1));
        g_avg[(mrow + t) * D_ + d] = __float2half_rn(x);
    }
}

// ---------------- conversions ------------------------------------------------
__global__ __launch_bounds__(256) void k_convert_iQ(const float* __restrict__ iQ) {
    size_t t = (size_t)blockIdx.x * blockDim.x + threadIdx.x;   // M_*D_/32 threads
    size_t m  = t / (D_ / 32);
    int    dq = (int)(t % (D_ / 32)) * 32;
    const float4* src = (const float4*)(iQ + m * D_ + dq);
    unsigned w[16];
#pragma unroll
    for (int i = 0; i < 8; i++) {
        float4 x = src[i];
        w[2 * i]     = pk_f16(x.x, x.y);
        w[2 * i + 1] = pk_f16(x.z, x.w);
    }
    uint4* dst = (uint4*)(g_q + m * D_ + dq);
#pragma unroll
    for (int i = 0; i < 4; i++)
        dst[i] = make_uint4(w[4 * i], w[4 * i + 1], w[4 * i + 2], w[4 * i + 3]);
}

// W [K,N] fp32 -> Wt [N, K] fp16, via smem transpose
__global__ __launch_bounds__(256) void k_convert_W(const float* __restrict__ W,
                                                   __half* __restrict__ Wt,
                                                   int K, int N) {
    __shared__ float t[64][65];
    const int tid = threadIdx.x;
    const int n0 = blockIdx.x * 64, k0 = blockIdx.y * 64;
    {
        const int r = tid >> 4;
        const int c4 = tid & 15;
#pragma unroll
        for (int i = 0; i < 4; i++) {
            int k = r + 16 * i;
            float4 v = *(const float4*)(W + (size_t)(k0 + k) * N + n0 + 4 * c4);
            t[k][4 * c4 + 0] = v.x;
            t[k][4 * c4 + 1] = v.y;
            t[k][4 * c4 + 2] = v.z;
            t[k][4 * c4 + 3] = v.w;
        }
    }
    __syncthreads();
    const int n = tid >> 2;
    const int kq = tid & 3;              // 16 orig-k each
    unsigned w[8];
#pragma unroll
    for (int j = 0; j < 8; j++)
        w[j] = pk_f16(t[16 * kq + 2 * j][n], t[16 * kq + 2 * j + 1][n]);
    uint4* dst = (uint4*)(Wt + (size_t)(n0 + n) * K + k0 + 16 * kq);
    dst[0] = make_uint4(w[0], w[1], w[2], w[3]);
    dst[1] = make_uint4(w[4], w[5], w[6], w[7]);
}

// ================= GEMM A: 128x128 tile, 256 threads, occ 2 ===================
// SEL 0: avg @ W1t -> relu+b1 -> g_h
// SEL 1: h   @ W2t -> +b2    -> g_f
#define BK 64
#define STAGES 3
#define STG_A (2 * 128 * 128)                // 32 KB per stage
#define SMEM_A (STAGES * STG_A)              // 96 KB

template <int SEL>
__global__ __launch_bounds__(256, 2)
void k_gemm_small(const __half* __restrict__ A0,
                  const __half* __restrict__ Bw,
                  const float* __restrict__ bias)
{
    extern __shared__ __align__(1024) char dsmem[];
    const unsigned sbase = smem_u32(dsmem);

    const int tid = threadIdx.x;
    const int warp = tid >> 5, lid = tid & 31;
    const int wm = warp >> 2;            // 0..1 -> 64 rows
    const int wn = warp & 3;             // 0..3 -> 32 cols
    const int m0 = blockIdx.y * 128;
    const int n0 = blockIdx.x * 128;
    const int NB = D_ / BK;              // 16

    const int lrow = tid >> 1;           // 0..127
    const int lcb  = (tid & 1) * 4;
    const int lswz = lrow & 7;

    float acc[4][4][4];
#pragma unroll
    for (int i = 0; i < 4; i++)
#pragma unroll
        for (int j = 0; j < 4; j++)
#pragma unroll
            for (int k = 0; k < 4; k++) acc[i][j][k] = 0.f;

    auto load_blk = [&](int kb, int stage) {
        unsigned sA = sbase + stage * STG_A;
        unsigned sB = sA + 128 * 128;
        unsigned long long ag =
            (unsigned long long)(A0 + (size_t)(m0 + lrow) * D_ + (size_t)kb * BK);
        unsigned asm_ = sA + lrow * 128;
#pragma unroll
        for (int i = 0; i < 4; i++) {
            int c = lcb + i;
            asm volatile("cp.async.cg.shared.global [%0], [%1], 16;"
                         :: "r"(asm_ + (unsigned)((c ^ lswz) << 4)), "l"(ag + c * 16) : "memory");
        }
        unsigned long long bg2 =
            (unsigned long long)(Bw + (size_t)(n0 + lrow) * D_ + (size_t)kb * BK);
        unsigned bsm = sB + lrow * 128;
#pragma unroll
        for (int i = 0; i < 4; i++) {
            int c = lcb + i;
            asm volatile("cp.async.cg.shared.global [%0], [%1], 16;"
                         :: "r"(bsm + (unsigned)((c ^ lswz) << 4)), "l"(bg2 + c * 16) : "memory");
        }
        asm volatile("cp.async.commit_group;" ::: "memory");
    };

    int arow[4], brow[2];
#pragma unroll
    for (int mt = 0; mt < 4; mt++)
        arow[mt] = wm * 64 + mt * 16 + (lid & 7) + ((lid >> 3) & 1) * 8;
    const int ahi = lid >> 4;
#pragma unroll
    for (int p = 0; p < 2; p++)
        brow[p] = wn * 32 + p * 16 + (lid & 7) + (lid >> 4) * 8;
    const int bhi = (lid >> 3) & 1;

#pragma unroll
    for (int s = 0; s < STAGES - 1; s++) load_blk(s, s);

    for (int kb = 0; kb < NB; kb++) {
        asm volatile("cp.async.wait_group %0;" :: "n"(STAGES - 2) : "memory");
        __syncthreads();
        if (kb + STAGES - 1 < NB) load_blk(kb + STAGES - 1, (kb + STAGES - 1) % STAGES);

        unsigned sA = sbase + (kb % STAGES) * STG_A;
        unsigned sB = sA + 128 * 128;
#pragma unroll
        for (int ks = 0; ks < 4; ks++) {
            unsigned a[4][4], b[2][4];
#pragma unroll
            for (int mt = 0; mt < 4; mt++)
                ldsm4(a[mt][0], a[mt][1], a[mt][2], a[mt][3],
                      sA + arow[mt] * 128 + (unsigned)(((2 * ks + ahi) ^ (arow[mt] & 7)) << 4));
#pragma unroll
            for (int p = 0; p < 2; p++)
                ldsm4(b[p][0], b[p][1], b[p][2], b[p][3],
                      sB + brow[p] * 128 + (unsigned)(((2 * ks + bhi) ^ (brow[p] & 7)) << 4));
#pragma unroll
            for (int mt = 0; mt < 4; mt++)
#pragma unroll
                for (int nt = 0; nt < 4; nt++)
                    mma_f16(acc[mt][nt], a[mt][0], a[mt][1], a[mt][2], a[mt][3],
                            b[nt >> 1][(nt & 1) * 2], b[nt >> 1][(nt & 1) * 2 + 1]);
        }
    }

    const int gid = lid >> 2, tig = lid & 3;
#pragma unroll
    for (int mt = 0; mt < 4; mt++) {
#pragma unroll
        for (int r2 = 0; r2 < 2; r2++) {
            const int m = m0 + wm * 64 + mt * 16 + gid + r2 * 8;
#pragma unroll
            for (int nt = 0; nt < 4; nt++) {
                const int n = n0 + wn * 32 + nt * 8 + 2 * tig;
                float2 bb = *(const float2*)(bias + n);
                float v0 = acc[mt][nt][r2 * 2 + 0] + bb.x;
                float v1 = acc[mt][nt][r2 * 2 + 1] + bb.y;
                if (SEL == 0) {
                    v0 = fmaxf(v0, 0.f); v1 = fmaxf(v1, 0.f);
                    *(unsigned*)(g_h + (size_t)m * D_ + n) = pk_f16(v0, v1);
                } else {
                    *(unsigned*)(g_f + (size_t)m * D_ + n) = pk_f16(v0, v1);
                }
            }
        }
    }
}

// ================= GEMM B: gate GEMM + combine (128x256, 512 thr) =============
// concat(q, f) @ Wgt (paired cols n, n+1024) -> sigmoid -> smem exchange ->
// out = igate*q + fgate*f       (q, f read as fp16)
#define BM 128
#define BN 256
#define A_BYTES (BM * 128)                  // 16 KB
#define B_BYTES (BN * 128)                  // 32 KB
#define STG_B (A_BYTES + B_BYTES)           // 48 KB
#define SMEM_B (STAGES * STG_B)             // 144 KB

__global__ __launch_bounds__(512, 1)
void k_gemm_gate(const __half* __restrict__ A0,     // g_q
                 const __half* __restrict__ A1,     // g_f
                 const __half* __restrict__ Bw,     // g_Wgt
                 const float* __restrict__ bias,
                 float* __restrict__ out)
{
    extern __shared__ __align__(1024) char dsmem[];
    const unsigned sbase = smem_u32(dsmem);
    const int K = 2 * D_;

    const int tid = threadIdx.x;
    const int warp = tid >> 5, lid = tid & 31;
    const int wm = warp >> 3;            // 0..1
    const int wn = warp & 7;             // 0..7
    const int m0 = blockIdx.y * BM;
    const int cg0 = blockIdx.x * 128;    // gate col-pair base
    const int NB = K / BK;               // 32

    const int ar  = tid >> 2;            // 0..127
    const int ac0 = (tid & 3) * 2;
    const int br  = tid >> 1;            // 0..255
    const int bc0 = (tid & 1) * 4;

    float acc[4][4][4];
#pragma unroll
    for (int i = 0; i < 4; i++)
#pragma unroll
        for (int j = 0; j < 4; j++)
#pragma unroll
            for (int k = 0; k < 4; k++) acc[i][j][k] = 0.f;

    auto load_blk = [&](int kb, int stage) {
        unsigned sA = sbase + stage * STG_B;
        unsigned sB = sA + A_BYTES;
        const __half* Arow;
        if (kb >= 16) Arow = A1 + (size_t)(m0 + ar) * D_ + (size_t)(kb - 16) * BK;
        else          Arow = A0 + (size_t)(m0 + ar) * D_ + (size_t)kb * BK;
        unsigned long long ag = (unsigned long long)Arow;
        unsigned asm_ = sA + ar * 128;
        const int aswz = ar & 7;
#pragma unroll
        for (int i = 0; i < 2; i++) {
            int c = ac0 + i;
            asm volatile("cp.async.cg.shared.global [%0], [%1], 16;"
                         :: "r"(asm_ + (unsigned)((c ^ aswz) << 4)), "l"(ag + c * 16) : "memory");
        }
        int gn = (br < 128) ? (cg0 + br) : (1024 + cg0 + br - 128);
        unsigned long long bg2 = (unsigned long long)(Bw + (size_t)gn * K + (size_t)kb * BK);
        unsigned bsm = sB + br * 128;
        const int bswz = br & 7;
#pragma unroll
        for (int i = 0; i < 4; i++) {
            int c = bc0 + i;
            asm volatile("cp.async.cg.shared.global [%0], [%1], 16;"
                         :: "r"(bsm + (unsigned)((c ^ bswz) << 4)), "l"(bg2 + c * 16) : "memory");
        }
        asm volatile("cp.async.commit_group;" ::: "memory");
    };

    int arow[4], brow[2];
#pragma unroll
    for (int mt = 0; mt < 4; mt++)
        arow[mt] = wm * 64 + mt * 16 + (lid & 7) + ((lid >> 3) & 1) * 8;
    const int ahi = lid >> 4;
#pragma unroll
    for (int p = 0; p < 2; p++)
        brow[p] = wn * 32 + p * 16 + (lid & 7) + (lid >> 4) * 8;
    const int bhi = (lid >> 3) & 1;

#pragma unroll
    for (int s = 0; s < STAGES - 1; s++) load_blk(s, s);

    for (int kb = 0; kb < NB; kb++) {
        asm volatile("cp.async.wait_group %0;" :: "n"(STAGES - 2) : "memory");
        __syncthreads();
        if (kb + STAGES - 1 < NB) load_blk(kb + STAGES - 1, (kb + STAGES - 1) % STAGES);

        unsigned sA = sbase + (kb % STAGES) * STG_B;
        unsigned sB = sA + A_BYTES;
#pragma unroll
        for (int ks = 0; ks < 4; ks++) {
            unsigned a[4][4], b[2][4];
#pragma unroll
            for (int mt = 0; mt < 4; mt++)
                ldsm4(a[mt][0], a[mt][1], a[mt][2], a[mt][3],
                      sA + arow[mt] * 128 + (unsigned)(((2 * ks + ahi) ^ (arow[mt] & 7)) << 4));
#pragma unroll
            for (int p = 0; p < 2; p++)
                ldsm4(b[p][0], b[p][1], b[p][2], b[p][3],
                      sB + brow[p] * 128 + (unsigned)(((2 * ks + bhi) ^ (brow[p] & 7)) << 4));
#pragma unroll
            for (int mt = 0; mt < 4; mt++)
#pragma unroll
                for (int nt = 0; nt < 4; nt++)
                    mma_f16(acc[mt][nt], a[mt][0], a[mt][1], a[mt][2], a[mt][3],
                            b[nt >> 1][(nt & 1) * 2], b[nt >> 1][(nt & 1) * 2 + 1]);
        }
    }

    // gate exchange + fused combine
    const int gid = lid >> 2, tig = lid & 3;
    __syncthreads();
    float* gsm = (float*)dsmem;        // [128][260]
#pragma unroll
    for (int mt = 0; mt < 4; mt++) {
#pragma unroll
        for (int r2 = 0; r2 < 2; r2++) {
            const int ml = wm * 64 + mt * 16 + gid + r2 * 8;
#pragma unroll
            for (int nt = 0; nt < 4; nt++) {
                const int nl = wn * 32 + nt * 8 + 2 * tig;
                const int gcol = (nl < 128) ? (cg0 + nl) : (1024 + cg0 + nl - 128);
                float2 bb = *(const float2*)(bias + gcol);
                float v0 = acc[mt][nt][r2 * 2 + 0] + bb.x;
                float v1 = acc[mt][nt][r2 * 2 + 1] + bb.y;
                v0 = 1.0f / (1.0f + __expf(-v0));
                v1 = 1.0f / (1.0f + __expf(-v1));
                gsm[ml * 260 + nl]     = v0;
                gsm[ml * 260 + nl + 1] = v1;
            }
        }
    }
    __syncthreads();
    const int c4 = tid & 31;            // float4 col group 0..31
    const int r0 = tid >> 5;            // 0..15
#pragma unroll
    for (int i = 0; i < 8; i++) {
        const int r = r0 + 16 * i;
        const int col = 4 * c4;
        const size_t gidx = (size_t)(m0 + r) * D_ + cg0 + col;
        uint2 qw = *(const uint2*)(A0 + gidx);      // 4 halves of q
        uint2 fw = *(const uint2*)(A1 + gidx);      // 4 halves of f
        float2 q01 = __half22float2(*(__half2*)&qw.x);
        float2 q23 = __half22float2(*(__half2*)&qw.y);
        float2 f01 = __half22float2(*(__half2*)&fw.x);
        float2 f23 = __half22float2(*(__half2*)&fw.y);
        float4 gi = *(const float4*)&gsm[r * 260 + col];
        float4 gf = *(const float4*)&gsm[r * 260 + 128 + col];
        float4 o;
        o.x = gi.x * q01.x + gf.x * f01.x;
        o.y = gi.y * q01.y + gf.y * f01.y;
        o.z = gi.z * q23.x + gf.z * f23.x;
        o.w = gi.w * q23.y + gf.w * f23.y;
        *(float4*)(out + gidx) = o;
    }
}

// ---------------- launch ------------------------------------------------------
extern "C" void kernel_launch(void* const* d_in, const int* in_sizes, int n_in,
                              void* d_out, int out_size) {
    const float* iQ = (const float*)d_in[0];
    const float* iV = (const float*)d_in[1];
    const float* W1 = (const float*)d_in[2];
    const float* b1 = (const float*)d_in[3];
    const float* W2 = (const float*)d_in[4];
    const float* b2 = (const float*)d_in[5];
    const float* Wg = (const float*)d_in[6];
    const float* bg = (const float*)d_in[7];
    float* out = (float*)d_out;

    cudaFuncSetAttribute(k_gemm_small<0>, cudaFuncAttributeMaxDynamicSharedMemorySize, SMEM_A);
    cudaFuncSetAttribute(k_gemm_small<1>, cudaFuncAttributeMaxDynamicSharedMemorySize, SMEM_A);
    cudaFuncSetAttribute(k_gemm_gate, cudaFuncAttributeMaxDynamicSharedMemorySize, SMEM_B);

    __half *w1t, *w2t, *wgt, *q, *avg, *h, *f;
    cudaGetSymbolAddress((void**)&w1t, g_W1t);
    cudaGetSymbolAddress((void**)&w2t, g_W2t);
    cudaGetSymbolAddress((void**)&wgt, g_Wgt);
    cudaGetSymbolAddress((void**)&q,   g_q);
    cudaGetSymbolAddress((void**)&avg, g_avg);
    cudaGetSymbolAddress((void**)&h,   g_h);
    cudaGetSymbolAddress((void**)&f,   g_f);

    // operand prep
    k_convert_iQ<<<(M_ * D_ / 32) / 256, 256>>>(iQ);
    k_convert_W<<<dim3(D_ / 64, D_ / 64), 256>>>(W1, w1t, D_, D_);
    k_convert_W<<<dim3(D_ / 64, D_ / 64), 256>>>(W2, w2t, D_, D_);
    k_convert_W<<<dim3(2 * D_ / 64, 2 * D_ / 64), 256>>>(Wg, wgt, 2 * D_, 2 * D_);

    // causal cumulative mean -> g_avg
    k_partial_sums<<<dim3(B_, NCH), D_>>>(iV);
    k_exclusive_prefix<<<B_, D_>>>();
    k_cumavg<<<dim3(B_, NCH), D_>>>(iV);

    // h = relu(avg @ W1 + b1)
    k_gemm_small<0><<<dim3(D_ / 128, M_ / 128), 256, SMEM_A>>>(avg, w1t, b1);
    // f = fp16(h @ W2 + b2)
    k_gemm_small<1><<<dim3(D_ / 128, M_ / 128), 256, SMEM_A>>>(h, w2t, b2);
    // out = sigmoid-gate GEMM + combine
    k_gemm_gate<<<dim3(2 * D_ / BN, M_ / BM), 512, SMEM_B>>>(q, f, wgt, bg, out);
}

// round 13
// speedup vs baseline: 2.9276x; 1.0396x over previous
#include <cuda_runtime.h>
#include <cuda_fp16.h>

#define B_   4
#define S_   2048
#define D_   1024
#define M_   (B_ * S_)          // 8192
#define NCH  64
#define CH   (S_ / NCH)         // 32

// ---------------- scratch ----------------------------------------------------
__device__ __align__(256) __half g_q  [(size_t)M_ * D_];
__device__ __align__(256) __half g_avg[(size_t)M_ * D_];
__device__ __align__(256) __half g_h  [(size_t)M_ * D_];
__device__ __align__(256) __half g_f  [(size_t)M_ * D_];
__device__ __align__(256) __half g_W1t[(size_t)D_ * D_];        // [N, K]
__device__ __align__(256) __half g_W2t[(size_t)D_ * D_];
__device__ __align__(256) __half g_Wgt[(size_t)2 * D_ * 2 * D_];
__device__ float g_part[B_ * NCH * D_];

// ---------------- helpers ----------------------------------------------------
__device__ __forceinline__ unsigned smem_u32(const void* p) {
    unsigned r;
    asm("{ .reg .u64 t; cvta.to.shared.u64 t, %1; cvt.u32.u64 %0, t; }" : "=r"(r) : "l"(p));
    return r;
}
__device__ __forceinline__ unsigned pk_f16(float a, float b) {
    return (unsigned)__half_as_ushort(__float2half_rn(a)) |
           ((unsigned)__half_as_ushort(__float2half_rn(b)) << 16);
}
__device__ __forceinline__ void ldsm4(unsigned& r0, unsigned& r1, unsigned& r2, unsigned& r3,
                                      unsigned addr) {
    asm volatile("ldmatrix.sync.aligned.m8n8.x4.shared.b16 {%0,%1,%2,%3}, [%4];"
                 : "=r"(r0), "=r"(r1), "=r"(r2), "=r"(r3) : "r"(addr));
}
__device__ __forceinline__ void mma_f16(float* c, unsigned a0, unsigned a1, unsigned a2,
                                        unsigned a3, unsigned b0, unsigned b1) {
    asm volatile(
        "mma.sync.aligned.m16n8k16.row.col.f32.f16.f16.f32 "
        "{%0,%1,%2,%3}, {%4,%5,%6,%7}, {%8,%9}, {%0,%1,%2,%3};"
        : "+f"(c[0]), "+f"(c[1]), "+f"(c[2]), "+f"(c[3])
        : "r"(a0), "r"(a1), "r"(a2), "r"(a3), "r"(b0), "r"(b1));
}

// ---------------- scan: causal cumulative mean -------------------------------
__global__ void k_partial_sums(const float* __restrict__ iV) {
    int b = blockIdx.x, ch = blockIdx.y, d = threadIdx.x;
    const float* p = iV + ((size_t)b * S_ + (size_t)ch * CH) * D_ + d;
    float s = 0.f;
#pragma unroll 8
    for (int t = 0; t < CH; t++) s += p[(size_t)t * D_];
    g_part[(b * NCH + ch) * D_ + d] = s;
}

__global__ void k_exclusive_prefix() {
    int b = blockIdx.x, d = threadIdx.x;
    float run = 0.f;
#pragma unroll
    for (int ch = 0; ch < NCH; ch++) {
        int idx = (b * NCH + ch) * D_ + d;
        float v = g_part[idx];
        g_part[idx] = run;
        run += v;
    }
}

__global__ void k_cumavg(const float* __restrict__ iV) {
    int b = blockIdx.x, ch = blockIdx.y, d = threadIdx.x;
    float run = g_part[(b * NCH + ch) * D_ + d];
    const float* p = iV + ((size_t)b * S_ + (size_t)ch * CH) * D_ + d;
    size_t mrow = (size_t)b * S_ + (size_t)ch * CH;
#pragma unroll 4
    for (int t = 0; t < CH; t++) {
        run += p[(size_t)t * D_];
        int s = ch * CH + t;
        float x = run * (1.0f / (float)(s + 1));
        g_avg[(mrow + t) * D_ + d] = __float2half_rn(x);
    }
}

// ---------------- conversions ------------------------------------------------
__global__ __launch_bounds__(256) void k_convert_iQ(const float* __restrict__ iQ) {
    size_t t = (size_t)blockIdx.x * blockDim.x + threadIdx.x;   // M_*D_/32 threads
    size_t m  = t / (D_ / 32);
    int    dq = (int)(t % (D_ / 32)) * 32;
    const float4* src = (const float4*)(iQ + m * D_ + dq);
    unsigned w[16];
#pragma unroll
    for (int i = 0; i < 8; i++) {
        float4 x = src[i];
        w[2 * i]     = pk_f16(x.x, x.y);
        w[2 * i + 1] = pk_f16(x.z, x.w);
    }
    uint4* dst = (uint4*)(g_q + m * D_ + dq);
#pragma unroll
    for (int i = 0; i < 4; i++)
        dst[i] = make_uint4(w[4 * i], w[4 * i + 1], w[4 * i + 2], w[4 * i + 3]);
}

// W [K,N] fp32 -> Wt [N, K] fp16, via smem transpose
__global__ __launch_bounds__(256) void k_convert_W(const float* __restrict__ W,
                                                   __half* __restrict__ Wt,
                                                   int K, int N) {
    __shared__ float t[64][65];
    const int tid = threadIdx.x;
    const int n0 = blockIdx.x * 64, k0 = blockIdx.y * 64;
    {
        const int r = tid >> 4;
        const int c4 = tid & 15;
#pragma unroll
        for (int i = 0; i < 4; i++) {
            int k = r + 16 * i;
            float4 v = *(const float4*)(W + (size_t)(k0 + k) * N + n0 + 4 * c4);
            t[k][4 * c4 + 0] = v.x;
            t[k][4 * c4 + 1] = v.y;
            t[k][4 * c4 + 2] = v.z;
            t[k][4 * c4 + 3] = v.w;
        }
    }
    __syncthreads();
    const int n = tid >> 2;
    const int kq = tid & 3;              // 16 orig-k each
    unsigned w[8];
#pragma unroll
    for (int j = 0; j < 8; j++)
        w[j] = pk_f16(t[16 * kq + 2 * j][n], t[16 * kq + 2 * j + 1][n]);
    uint4* dst = (uint4*)(Wt + (size_t)(n0 + n) * K + k0 + 16 * kq);
    dst[0] = make_uint4(w[0], w[1], w[2], w[3]);
    dst[1] = make_uint4(w[4], w[5], w[6], w[7]);
}

// ================= GEMM A: 128x128 tile, 256 threads, occ 2 ===================
#define BK 64
#define STAGES 3
#define STG_A (2 * 128 * 128)                // 32 KB per stage
#define SMEM_A (STAGES * STG_A)              // 96 KB

template <int SEL>
__global__ __launch_bounds__(256, 2)
void k_gemm_small(const __half* __restrict__ A0,
                  const __half* __restrict__ Bw,
                  const float* __restrict__ bias)
{
    extern __shared__ __align__(1024) char dsmem[];
    const unsigned sbase = smem_u32(dsmem);

    const int tid = threadIdx.x;
    const int warp = tid >> 5, lid = tid & 31;
    const int wm = warp >> 2;            // 0..1 -> 64 rows
    const int wn = warp & 3;             // 0..3 -> 32 cols
    const int m0 = blockIdx.y * 128;
    const int n0 = blockIdx.x * 128;
    const int NB = D_ / BK;              // 16

    const int lrow = tid >> 1;           // 0..127
    const int lcb  = (tid & 1) * 4;
    const int lswz = lrow & 7;

    float acc[4][4][4];
#pragma unroll
    for (int i = 0; i < 4; i++)
#pragma unroll
        for (int j = 0; j < 4; j++)
#pragma unroll
            for (int k = 0; k < 4; k++) acc[i][j][k] = 0.f;

    auto load_blk = [&](int kb, int stage) {
        unsigned sA = sbase + stage * STG_A;
        unsigned sB = sA + 128 * 128;
        unsigned long long ag =
            (unsigned long long)(A0 + (size_t)(m0 + lrow) * D_ + (size_t)kb * BK);
        unsigned asm_ = sA + lrow * 128;
#pragma unroll
        for (int i = 0; i < 4; i++) {
            int c = lcb + i;
            asm volatile("cp.async.cg.shared.global [%0], [%1], 16;"
                         :: "r"(asm_ + (unsigned)((c ^ lswz) << 4)), "l"(ag + c * 16) : "memory");
        }
        unsigned long long bg2 =
            (unsigned long long)(Bw + (size_t)(n0 + lrow) * D_ + (size_t)kb * BK);
        unsigned bsm = sB + lrow * 128;
#pragma unroll
        for (int i = 0; i < 4; i++) {
            int c = lcb + i;
            asm volatile("cp.async.cg.shared.global [%0], [%1], 16;"
                         :: "r"(bsm + (unsigned)((c ^ lswz) << 4)), "l"(bg2 + c * 16) : "memory");
        }
        asm volatile("cp.async.commit_group;" ::: "memory");
    };

    int arow[4], brow[2];
#pragma unroll
    for (int mt = 0; mt < 4; mt++)
        arow[mt] = wm * 64 + mt * 16 + (lid & 7) + ((lid >> 3) & 1) * 8;
    const int ahi = lid >> 4;
#pragma unroll
    for (int p = 0; p < 2; p++)
        brow[p] = wn * 32 + p * 16 + (lid & 7) + (lid >> 4) * 8;
    const int bhi = (lid >> 3) & 1;

#pragma unroll
    for (int s = 0; s < STAGES - 1; s++) load_blk(s, s);

    for (int kb = 0; kb < NB; kb++) {
        asm volatile("cp.async.wait_group %0;" :: "n"(STAGES - 2) : "memory");
        __syncthreads();
        if (kb + STAGES - 1 < NB) load_blk(kb + STAGES - 1, (kb + STAGES - 1) % STAGES);

        unsigned sA = sbase + (kb % STAGES) * STG_A;
        unsigned sB = sA + 128 * 128;
#pragma unroll
        for (int ks = 0; ks < 4; ks++) {
            unsigned a[4][4], b[2][4];
#pragma unroll
            for (int mt = 0; mt < 4; mt++)
                ldsm4(a[mt][0], a[mt][1], a[mt][2], a[mt][3],
                      sA + arow[mt] * 128 + (unsigned)(((2 * ks + ahi) ^ (arow[mt] & 7)) << 4));
#pragma unroll
            for (int p = 0; p < 2; p++)
                ldsm4(b[p][0], b[p][1], b[p][2], b[p][3],
                      sB + brow[p] * 128 + (unsigned)(((2 * ks + bhi) ^ (brow[p] & 7)) << 4));
#pragma unroll
            for (int mt = 0; mt < 4; mt++)
#pragma unroll
                for (int nt = 0; nt < 4; nt++)
                    mma_f16(acc[mt][nt], a[mt][0], a[mt][1], a[mt][2], a[mt][3],
                            b[nt >> 1][(nt & 1) * 2], b[nt >> 1][(nt & 1) * 2 + 1]);
        }
    }

    const int gid = lid >> 2, tig = lid & 3;
#pragma unroll
    for (int mt = 0; mt < 4; mt++) {
#pragma unroll
        for (int r2 = 0; r2 < 2; r2++) {
            const int m = m0 + wm * 64 + mt * 16 + gid + r2 * 8;
#pragma unroll
            for (int nt = 0; nt < 4; nt++) {
                const int n = n0 + wn * 32 + nt * 8 + 2 * tig;
                float2 bb = *(const float2*)(bias + n);
                float v0 = acc[mt][nt][r2 * 2 + 0] + bb.x;
                float v1 = acc[mt][nt][r2 * 2 + 1] + bb.y;
                if (SEL == 0) {
                    v0 = fmaxf(v0, 0.f); v1 = fmaxf(v1, 0.f);
                    *(unsigned*)(g_h + (size_t)m * D_ + n) = pk_f16(v0, v1);
                } else {
                    *(unsigned*)(g_f + (size_t)m * D_ + n) = pk_f16(v0, v1);
                }
            }
        }
    }
}

// ================= GEMM B: gate GEMM + combine (128x256, 512 thr) =============
#define BM 128
#define BN 256
#define A_BYTES (BM * 128)                  // 16 KB
#define B_BYTES (BN * 128)                  // 32 KB
#define STG_B (A_BYTES + B_BYTES)           // 48 KB
#define SMEM_B (STAGES * STG_B)             // 144 KB

__global__ __launch_bounds__(512, 1)
void k_gemm_gate(const __half* __restrict__ A0,     // g_q
                 const __half* __restrict__ A1,     // g_f
                 const __half* __restrict__ Bw,     // g_Wgt
                 const float* __restrict__ bias,
                 float* __restrict__ out)
{
    extern __shared__ __align__(1024) char dsmem[];
    const unsigned sbase = smem_u32(dsmem);
    const int K = 2 * D_;

    const int tid = threadIdx.x;
    const int warp = tid >> 5, lid = tid & 31;
    const int wm = warp >> 3;            // 0..1
    const int wn = warp & 7;             // 0..7
    const int m0 = blockIdx.y * BM;
    const int cg0 = blockIdx.x * 128;    // gate col-pair base
    const int NB = K / BK;               // 32

    const int ar  = tid >> 2;            // 0..127
    const int ac0 = (tid & 3) * 2;
    const int br  = tid >> 1;            // 0..255
    const int bc0 = (tid & 1) * 4;

    float acc[4][4][4];
#pragma unroll
    for (int i = 0; i < 4; i++)
#pragma unroll
        for (int j = 0; j < 4; j++)
#pragma unroll
            for (int k = 0; k < 4; k++) acc[i][j][k] = 0.f;

    auto load_blk = [&](int kb, int stage) {
        unsigned sA = sbase + stage * STG_B;
        unsigned sB = sA + A_BYTES;
        const __half* Arow;
        if (kb >= 16) Arow = A1 + (size_t)(m0 + ar) * D_ + (size_t)(kb - 16) * BK;
        else          Arow = A0 + (size_t)(m0 + ar) * D_ + (size_t)kb * BK;
        unsigned long long ag = (unsigned long long)Arow;
        unsigned asm_ = sA + ar * 128;
        const int aswz = ar & 7;
#pragma unroll
        for (int i = 0; i < 2; i++) {
            int c = ac0 + i;
            asm volatile("cp.async.cg.shared.global [%0], [%1], 16;"
                         :: "r"(asm_ + (unsigned)((c ^ aswz) << 4)), "l"(ag + c * 16) : "memory");
        }
        int gn = (br < 128) ? (cg0 + br) : (1024 + cg0 + br - 128);
        unsigned long long bg2 = (unsigned long long)(Bw + (size_t)gn * K + (size_t)kb * BK);
        unsigned bsm = sB + br * 128;
        const int bswz = br & 7;
#pragma unroll
        for (int i = 0; i < 4; i++) {
            int c = bc0 + i;
            asm volatile("cp.async.cg.shared.global [%0], [%1], 16;"
                         :: "r"(bsm + (unsigned)((c ^ bswz) << 4)), "l"(bg2 + c * 16) : "memory");
        }
        asm volatile("cp.async.commit_group;" ::: "memory");
    };

    int arow[4], brow[2];
#pragma unroll
    for (int mt = 0; mt < 4; mt++)
        arow[mt] = wm * 64 + mt * 16 + (lid & 7) + ((lid >> 3) & 1) * 8;
    const int ahi = lid >> 4;
#pragma unroll
    for (int p = 0; p < 2; p++)
        brow[p] = wn * 32 + p * 16 + (lid & 7) + (lid >> 4) * 8;
    const int bhi = (lid >> 3) & 1;

#pragma unroll
    for (int s = 0; s < STAGES - 1; s++) load_blk(s, s);

    for (int kb = 0; kb < NB; kb++) {
        asm volatile("cp.async.wait_group %0;" :: "n"(STAGES - 2) : "memory");
        __syncthreads();
        if (kb + STAGES - 1 < NB) load_blk(kb + STAGES - 1, (kb + STAGES - 1) % STAGES);

        unsigned sA = sbase + (kb % STAGES) * STG_B;
        unsigned sB = sA + A_BYTES;
#pragma unroll
        for (int ks = 0; ks < 4; ks++) {
            unsigned a[4][4], b[2][4];
#pragma unroll
            for (int mt = 0; mt < 4; mt++)
                ldsm4(a[mt][0], a[mt][1], a[mt][2], a[mt][3],
                      sA + arow[mt] * 128 + (unsigned)(((2 * ks + ahi) ^ (arow[mt] & 7)) << 4));
#pragma unroll
            for (int p = 0; p < 2; p++)
                ldsm4(b[p][0], b[p][1], b[p][2], b[p][3],
                      sB + brow[p] * 128 + (unsigned)(((2 * ks + bhi) ^ (brow[p] & 7)) << 4));
#pragma unroll
            for (int mt = 0; mt < 4; mt++)
#pragma unroll
                for (int nt = 0; nt < 4; nt++)
                    mma_f16(acc[mt][nt], a[mt][0], a[mt][1], a[mt][2], a[mt][3],
                            b[nt >> 1][(nt & 1) * 2], b[nt >> 1][(nt & 1) * 2 + 1]);
        }
    }

    // gate exchange + fused combine
    const int gid = lid >> 2, tig = lid & 3;
    __syncthreads();
    float* gsm = (float*)dsmem;        // [128][260]
#pragma unroll
    for (int mt = 0; mt < 4; mt++) {
#pragma unroll
        for (int r2 = 0; r2 < 2; r2++) {
            const int ml = wm * 64 + mt * 16 + gid + r2 * 8;
#pragma unroll
            for (int nt = 0; nt < 4; nt++) {
                const int nl = wn * 32 + nt * 8 + 2 * tig;
                const int gcol = (nl < 128) ? (cg0 + nl) : (1024 + cg0 + nl - 128);
                float2 bb = *(const float2*)(bias + gcol);
                float v0 = acc[mt][nt][r2 * 2 + 0] + bb.x;
                float v1 = acc[mt][nt][r2 * 2 + 1] + bb.y;
                v0 = 1.0f / (1.0f + __expf(-v0));
                v1 = 1.0f / (1.0f + __expf(-v1));
                gsm[ml * 260 + nl]     = v0;
                gsm[ml * 260 + nl + 1] = v1;
            }
        }
    }
    __syncthreads();
    const int c4 = tid & 31;
    const int r0 = tid >> 5;
#pragma unroll
    for (int i = 0; i < 8; i++) {
        const int r = r0 + 16 * i;
        const int col = 4 * c4;
        const size_t gidx = (size_t)(m0 + r) * D_ + cg0 + col;
        uint2 qw = *(const uint2*)(A0 + gidx);
        uint2 fw = *(const uint2*)(A1 + gidx);
        float2 q01 = __half22float2(*(__half2*)&qw.x);
        float2 q23 = __half22float2(*(__half2*)&qw.y);
        float2 f01 = __half22float2(*(__half2*)&fw.x);
        float2 f23 = __half22float2(*(__half2*)&fw.y);
        float4 gi = *(const float4*)&gsm[r * 260 + col];
        float4 gf = *(const float4*)&gsm[r * 260 + 128 + col];
        float4 o;
        o.x = gi.x * q01.x + gf.x * f01.x;
        o.y = gi.y * q01.y + gf.y * f01.y;
        o.z = gi.z * q23.x + gf.z * f23.x;
        o.w = gi.w * q23.y + gf.w * f23.y;
        *(float4*)(out + gidx) = o;
    }
}

// ---------------- launch ------------------------------------------------------
extern "C" void kernel_launch(void* const* d_in, const int* in_sizes, int n_in,
                              void* d_out, int out_size) {
    const float* iQ = (const float*)d_in[0];
    const float* iV = (const float*)d_in[1];
    const float* W1 = (const float*)d_in[2];
    const float* b1 = (const float*)d_in[3];
    const float* W2 = (const float*)d_in[4];
    const float* b2 = (const float*)d_in[5];
    const float* Wg = (const float*)d_in[6];
    const float* bg = (const float*)d_in[7];
    float* out = (float*)d_out;

    // one-time resources (host-side only; no device memory)
    static cudaStream_t s1 = nullptr, s2 = nullptr;
    static cudaEvent_t evRoot, evScan, evW2, evPrep;
    if (s1 == nullptr) {
        cudaStreamCreateWithFlags(&s1, cudaStreamNonBlocking);
        cudaStreamCreateWithFlags(&s2, cudaStreamNonBlocking);
        cudaEventCreateWithFlags(&evRoot, cudaEventDisableTiming);
        cudaEventCreateWithFlags(&evScan, cudaEventDisableTiming);
        cudaEventCreateWithFlags(&evW2,   cudaEventDisableTiming);
        cudaEventCreateWithFlags(&evPrep, cudaEventDisableTiming);
        cudaFuncSetAttribute(k_gemm_small<0>, cudaFuncAttributeMaxDynamicSharedMemorySize, SMEM_A);
        cudaFuncSetAttribute(k_gemm_small<1>, cudaFuncAttributeMaxDynamicSharedMemorySize, SMEM_A);
        cudaFuncSetAttribute(k_gemm_gate, cudaFuncAttributeMaxDynamicSharedMemorySize, SMEM_B);
    }

    __half *w1t, *w2t, *wgt, *q, *avg, *h, *f;
    cudaGetSymbolAddress((void**)&w1t, g_W1t);
    cudaGetSymbolAddress((void**)&w2t, g_W2t);
    cudaGetSymbolAddress((void**)&wgt, g_Wgt);
    cudaGetSymbolAddress((void**)&q,   g_q);
    cudaGetSymbolAddress((void**)&avg, g_avg);
    cudaGetSymbolAddress((void**)&h,   g_h);
    cudaGetSymbolAddress((void**)&f,   g_f);

    // fork
    cudaEventRecord(evRoot, 0);
    cudaStreamWaitEvent(s1, evRoot, 0);
    cudaStreamWaitEvent(s2, evRoot, 0);

    // branch s1: causal cumulative mean -> g_avg
    k_partial_sums<<<dim3(B_, NCH), D_, 0, s1>>>(iV);
    k_exclusive_prefix<<<B_, D_, 0, s1>>>();
    k_cumavg<<<dim3(B_, NCH), D_, 0, s1>>>(iV);
    cudaEventRecord(evScan, s1);

    // branch s2: converts needed by GEMM2 / GEMM3
    k_convert_W<<<dim3(D_ / 64, D_ / 64), 256, 0, s2>>>(W2, w2t, D_, D_);
    cudaEventRecord(evW2, s2);
    k_convert_W<<<dim3(2 * D_ / 64, 2 * D_ / 64), 256, 0, s2>>>(Wg, wgt, 2 * D_, 2 * D_);
    k_convert_iQ<<<(M_ * D_ / 32) / 256, 256, 0, s2>>>(iQ);
    cudaEventRecord(evPrep, s2);

    // main stream: W1 convert, then GEMM chain with event joins
    k_convert_W<<<dim3(D_ / 64, D_ / 64), 256>>>(W1, w1t, D_, D_);
    cudaStreamWaitEvent(0, evScan, 0);
    k_gemm_small<0><<<dim3(D_ / 128, M_ / 128), 256, SMEM_A>>>(avg, w1t, b1);
    cudaStreamWaitEvent(0, evW2, 0);
    k_gemm_small<1><<<dim3(D_ / 128, M_ / 128), 256, SMEM_A>>>(h, w2t, b2);
    cudaStreamWaitEvent(0, evPrep, 0);
    k_gemm_gate<<<dim3(2 * D_ / BN, M_ / BM), 512, SMEM_B>>>(q, f, wgt, bg, out);
}